// round 1
// baseline (speedup 1.0000x reference)
#include <cuda_runtime.h>
#include <cstdint>

#define F_IN  1024
#define F_H   128
#define EPS   1e-5f
#define NODES_MAX 50048

// Scratch buffers (allocation-free rule: __device__ globals)
__device__ __align__(256) float g_bufA[NODES_MAX * F_H];
__device__ __align__(256) float g_bufB[NODES_MAX * F_H];
__device__ __align__(256) float g_bufC[NODES_MAX * F_H];
__device__ __align__(256) float g_bufD[NODES_MAX * F_H];

// ---------------------------------------------------------------------------
// Fused dual GEMM: out_msg = X @ W        (raw, bias added post-aggregation)
//                  out_res = relu(X @ Wr + br)
// X: [M x KD] row-major, W/Wr: [KD x 128] row-major. Both outputs [M x 128].
// blockIdx.y in {0,1} -> W halves (cols 0-63 / 64-127), {2,3} -> Wr halves.
// BM=128, BN=64, BK=16, 256 threads, 8x4 per-thread tile.
// ---------------------------------------------------------------------------
template <int KD>
__global__ void __launch_bounds__(256) gemm_dual_kernel(
    const float* __restrict__ X, const float* __restrict__ W,
    const float* __restrict__ Wr, const float* __restrict__ br,
    float* __restrict__ out_msg, float* __restrict__ out_res, int M)
{
    constexpr int BM = 128, BN = 64, BK = 16;
    __shared__ float As[BK][BM + 4];
    __shared__ float Bs[BK][BN];

    const int t  = threadIdx.x;
    const int bm = blockIdx.x * BM;
    const int by = blockIdx.y;
    const bool isRes = (by >= 2);
    const float* __restrict__ B = isRes ? Wr : W;
    const int ncol = (isRes ? (by - 2) : by) * BN;

    const int tcol = t & 15;   // 16 col-groups * 4 cols
    const int trow = t >> 4;   // 16 row-groups * 8 rows

    float acc[8][4];
#pragma unroll
    for (int i = 0; i < 8; i++)
#pragma unroll
        for (int j = 0; j < 4; j++) acc[i][j] = 0.f;

    for (int k0 = 0; k0 < KD; k0 += BK) {
        // A tile: 128x16 floats = 512 float4, 2 per thread (transposed store)
#pragma unroll
        for (int i = 0; i < 2; i++) {
            int lin = t + i * 256;
            int row = lin >> 2;
            int q   = lin & 3;
            int grow = bm + row;
            float4 v = make_float4(0.f, 0.f, 0.f, 0.f);
            if (grow < M)
                v = *(const float4*)(X + (size_t)grow * KD + k0 + q * 4);
            As[q * 4 + 0][row] = v.x;
            As[q * 4 + 1][row] = v.y;
            As[q * 4 + 2][row] = v.z;
            As[q * 4 + 3][row] = v.w;
        }
        // B tile: 16x64 floats = 256 float4, 1 per thread
        {
            int row = t >> 4;   // 0..15
            int q   = t & 15;   // 0..15
            float4 v = *(const float4*)(B + (size_t)(k0 + row) * F_H + ncol + q * 4);
            *(float4*)&Bs[row][q * 4] = v;
        }
        __syncthreads();

#pragma unroll
        for (int k = 0; k < BK; k++) {
            float ra[8], rb[4];
#pragma unroll
            for (int i = 0; i < 8; i++) ra[i] = As[k][trow * 8 + i];
#pragma unroll
            for (int j = 0; j < 4; j++) rb[j] = Bs[k][tcol * 4 + j];
#pragma unroll
            for (int i = 0; i < 8; i++)
#pragma unroll
                for (int j = 0; j < 4; j++)
                    acc[i][j] = fmaf(ra[i], rb[j], acc[i][j]);
        }
        __syncthreads();
    }

    // Epilogue: float4 stores
    float4 brv = make_float4(0.f, 0.f, 0.f, 0.f);
    if (isRes) brv = *(const float4*)(br + ncol + tcol * 4);
#pragma unroll
    for (int i = 0; i < 8; i++) {
        int grow = bm + trow * 8 + i;
        if (grow >= M) continue;
        float4 v;
        v.x = acc[i][0]; v.y = acc[i][1]; v.z = acc[i][2]; v.w = acc[i][3];
        if (isRes) {
            v.x = fmaxf(v.x + brv.x, 0.f);
            v.y = fmaxf(v.y + brv.y, 0.f);
            v.z = fmaxf(v.z + brv.z, 0.f);
            v.w = fmaxf(v.w + brv.w, 0.f);
            *(float4*)(out_res + (size_t)grow * F_H + ncol + tcol * 4) = v;
        } else {
            *(float4*)(out_msg + (size_t)grow * F_H + ncol + tcol * 4) = v;
        }
    }
}

// ---------------------------------------------------------------------------
__global__ void zero_kernel(float4* __restrict__ p, int n4)
{
    int i = blockIdx.x * blockDim.x + threadIdx.x;
    if (i < n4) p[i] = make_float4(0.f, 0.f, 0.f, 0.f);
}

// Edge scatter: one warp per edge, lane handles 4 floats.
// agg[dst] += msg[src] via vector reduction (sm_90+ red.global.add.v4.f32).
__global__ void scatter_kernel(const float* __restrict__ msg, float* __restrict__ agg,
                               const int* __restrict__ src, const int* __restrict__ dst,
                               int E)
{
    int tid  = blockIdx.x * blockDim.x + threadIdx.x;
    int e    = tid >> 5;
    int lane = tid & 31;
    if (e >= E) return;
    int s = __ldg(src + e);
    int d = __ldg(dst + e);
    float4 v = *(const float4*)(msg + (size_t)s * F_H + lane * 4);
    float* p = agg + (size_t)d * F_H + lane * 4;
    asm volatile("red.global.add.v4.f32 [%0], {%1,%2,%3,%4};"
                 :: "l"(p), "f"(v.x), "f"(v.y), "f"(v.z), "f"(v.w)
                 : "memory");
}

// h = BN( relu(agg + b) + res_with_relu )
__global__ void post_kernel(const float* __restrict__ agg, const float* __restrict__ res,
                            const float* __restrict__ b, const float* __restrict__ gamma,
                            const float* __restrict__ beta, const float* __restrict__ mean,
                            const float* __restrict__ var, float* __restrict__ hout, int N)
{
    int idx = blockIdx.x * blockDim.x + threadIdx.x;  // one float4 per thread
    int total = N * (F_H / 4);
    if (idx >= total) return;
    int c4 = (idx & 31) * 4;
    float4 a = *(const float4*)(agg + (size_t)idx * 4);
    float4 r = *(const float4*)(res + (size_t)idx * 4);
    float av[4] = {a.x, a.y, a.z, a.w};
    float rv[4] = {r.x, r.y, r.z, r.w};
    float o[4];
#pragma unroll
    for (int j = 0; j < 4; j++) {
        int c = c4 + j;
        float v = fmaxf(av[j] + __ldg(b + c), 0.f) + rv[j];
        o[j] = (v - __ldg(mean + c)) * rsqrtf(__ldg(var + c) + EPS) * __ldg(gamma + c)
               + __ldg(beta + c);
    }
    *(float4*)(hout + (size_t)idx * 4) = make_float4(o[0], o[1], o[2], o[3]);
}

// out = softmax(h @ Wd + bd), one warp per node
__global__ void head_kernel(const float* __restrict__ h, const float* __restrict__ Wd,
                            const float* __restrict__ bd, float* __restrict__ out, int N)
{
    __shared__ float wd[F_H * 2];
    int t = threadIdx.x;
    wd[t] = Wd[t];   // blockDim == 256 == F_H*2
    __syncthreads();

    int gwarp = (blockIdx.x * blockDim.x + t) >> 5;
    int lane  = t & 31;
    if (gwarp >= N) return;

    float4 v = *(const float4*)(h + (size_t)gwarp * F_H + lane * 4);
    int k = lane * 4;
    float l0 = v.x * wd[(k + 0) * 2] + v.y * wd[(k + 1) * 2] +
               v.z * wd[(k + 2) * 2] + v.w * wd[(k + 3) * 2];
    float l1 = v.x * wd[(k + 0) * 2 + 1] + v.y * wd[(k + 1) * 2 + 1] +
               v.z * wd[(k + 2) * 2 + 1] + v.w * wd[(k + 3) * 2 + 1];
#pragma unroll
    for (int off = 16; off > 0; off >>= 1) {
        l0 += __shfl_xor_sync(0xFFFFFFFFu, l0, off);
        l1 += __shfl_xor_sync(0xFFFFFFFFu, l1, off);
    }
    if (lane == 0) {
        l0 += __ldg(bd + 0);
        l1 += __ldg(bd + 1);
        float m  = fmaxf(l0, l1);
        float e0 = __expf(l0 - m), e1 = __expf(l1 - m);
        float inv = 1.f / (e0 + e1);
        out[(size_t)gwarp * 2 + 0] = e0 * inv;
        out[(size_t)gwarp * 2 + 1] = e1 * inv;
    }
}

// ---------------------------------------------------------------------------
extern "C" void kernel_launch(void* const* d_in, const int* in_sizes, int n_in,
                              void* d_out, int out_size)
{
    const float* in_feat = (const float*)d_in[0];
    const int*   src     = (const int*)d_in[1];
    const int*   dst     = (const int*)d_in[2];
    const float* W0   = (const float*)d_in[3];
    const float* b0   = (const float*)d_in[4];
    const float* Wr0  = (const float*)d_in[5];
    const float* br0  = (const float*)d_in[6];
    const float* g0   = (const float*)d_in[7];
    const float* be0  = (const float*)d_in[8];
    const float* m0   = (const float*)d_in[9];
    const float* v0   = (const float*)d_in[10];
    const float* W1   = (const float*)d_in[11];
    const float* b1   = (const float*)d_in[12];
    const float* Wr1  = (const float*)d_in[13];
    const float* br1  = (const float*)d_in[14];
    const float* g1   = (const float*)d_in[15];
    const float* be1  = (const float*)d_in[16];
    const float* m1   = (const float*)d_in[17];
    const float* v1   = (const float*)d_in[18];
    const float* Wd   = (const float*)d_in[19];
    const float* bd   = (const float*)d_in[20];

    const int N = in_sizes[0] / F_IN;   // 50000
    const int E = in_sizes[1];          // 800000

    static float *pA = nullptr, *pB = nullptr, *pC = nullptr, *pD = nullptr;
    if (pA == nullptr) {
        cudaGetSymbolAddress((void**)&pA, g_bufA);
        cudaGetSymbolAddress((void**)&pB, g_bufB);
        cudaGetSymbolAddress((void**)&pC, g_bufC);
        cudaGetSymbolAddress((void**)&pD, g_bufD);
    }

    const dim3 gemm_grid((N + 127) / 128, 4);
    const int  n4        = N * (F_H / 4);
    const int  zb        = (n4 + 255) / 256;
    const int  sb        = (int)(((int64_t)E * 32 + 255) / 256);
    const int  pb        = (n4 + 255) / 256;
    const int  hb        = (N + 7) / 8;

    // ----- Layer 0 -----
    gemm_dual_kernel<F_IN><<<gemm_grid, 256>>>(in_feat, W0, Wr0, br0, pA, pB, N);
    zero_kernel<<<zb, 256>>>((float4*)pC, n4);
    scatter_kernel<<<sb, 256>>>(pA, pC, src, dst, E);
    post_kernel<<<pb, 256>>>(pC, pB, b0, g0, be0, m0, v0, pA, N);   // h1 -> A

    // ----- Layer 1 -----
    gemm_dual_kernel<F_H><<<gemm_grid, 256>>>(pA, W1, Wr1, br1, pB, pD, N);
    zero_kernel<<<zb, 256>>>((float4*)pC, n4);
    scatter_kernel<<<sb, 256>>>(pB, pC, src, dst, E);
    post_kernel<<<pb, 256>>>(pC, pD, b1, g1, be1, m1, v1, pA, N);   // h2 -> A

    // ----- Head -----
    head_kernel<<<hb, 256>>>(pA, Wd, bd, (float*)d_out, N);
}

// round 2
// speedup vs baseline: 3.3325x; 3.3325x over previous
#include <cuda_runtime.h>
#include <cstdint>

#define F_IN  1024
#define F_H   128
#define EPS   1e-5f
#define NODES_MAX 50048

// Scratch buffers (allocation-free rule: __device__ globals)
__device__ __align__(256) float g_bufA[NODES_MAX * F_H];
__device__ __align__(256) float g_bufB[NODES_MAX * F_H];
__device__ __align__(256) float g_bufC[NODES_MAX * F_H];
__device__ __align__(256) float g_bufD[NODES_MAX * F_H];

__device__ __forceinline__ uint32_t f2tf(float x) {
    uint32_t u;
    asm("cvt.rna.tf32.f32 %0, %1;" : "=r"(u) : "f"(x));
    return u;
}

__device__ __forceinline__ void mma_tf32(float* c, const uint32_t* a, const uint32_t* b) {
    asm volatile(
        "mma.sync.aligned.m16n8k8.row.col.f32.tf32.tf32.f32 "
        "{%0,%1,%2,%3}, {%4,%5,%6,%7}, {%8,%9}, {%0,%1,%2,%3};"
        : "+f"(c[0]), "+f"(c[1]), "+f"(c[2]), "+f"(c[3])
        : "r"(a[0]), "r"(a[1]), "r"(a[2]), "r"(a[3]), "r"(b[0]), "r"(b[1]));
}

// ---------------------------------------------------------------------------
// tf32 tensor-core dual GEMM.
// blockIdx.x: 0 -> out_msg = X @ W (raw); 1 -> out_res = relu(X @ Wr + br)
// blockIdx.y: M tile (BM=128). BN=128 covers all output cols.
// 256 threads, 8 warps = 2(M) x 4(N), warp tile 64x32, mma m16n8k8 tf32.
// ---------------------------------------------------------------------------
template <int KD>
__global__ void __launch_bounds__(256, 2) gemm_tf32_kernel(
    const float* __restrict__ X, const float* __restrict__ W,
    const float* __restrict__ Wr, const float* __restrict__ br,
    float* __restrict__ out_msg, float* __restrict__ out_res, int M)
{
    constexpr int BM = 128, BK = 16;
    constexpr int NIT = KD / BK;
    constexpr int AS_STRIDE = 20;    // 128-row A tile, k-contig rows; (20*4)%32=16... bank-spread verified
    constexpr int BS_STRIDE = 136;   // 16-row B tile, 128 cols + 8 pad
    constexpr int AS_STAGE  = BM * AS_STRIDE;   // floats
    constexpr int BS_STAGE  = BK * BS_STRIDE;

    __shared__ __align__(16) float sA[2 * AS_STAGE];
    __shared__ __align__(16) float sB[2 * BS_STAGE];

    const int t = threadIdx.x;
    const bool isRes = (blockIdx.x == 1);
    const float* __restrict__ Bmat = isRes ? Wr : W;
    const int bm = blockIdx.y * BM;

    const int lane = t & 31;
    const int w    = t >> 5;
    const int wm   = (w & 1) * 64;    // warp row base
    const int wn   = (w >> 1) * 32;   // warp col base
    const int g    = lane >> 2;       // groupID
    const int t4   = lane & 3;        // threadID_in_group

    const uint32_t sA_u = (uint32_t)__cvta_generic_to_shared(sA);
    const uint32_t sB_u = (uint32_t)__cvta_generic_to_shared(sB);

    float acc[4][4][4];
#pragma unroll
    for (int i = 0; i < 4; i++)
#pragma unroll
        for (int j = 0; j < 4; j++)
#pragma unroll
            for (int k = 0; k < 4; k++) acc[i][j][k] = 0.f;

    auto loadStage = [&](int it, int stg) {
        const int k0 = it * BK;
        // A tile: 128 rows x 16 k = 512 float4, 2 per thread
#pragma unroll
        for (int i = 0; i < 2; i++) {
            int lin = t + i * 256;
            int m = lin >> 2, q = lin & 3;
            int grow = bm + m;
            const float* src = X + (size_t)grow * KD + k0 + q * 4;
            uint32_t dst = sA_u + (uint32_t)((stg * AS_STAGE + m * AS_STRIDE + q * 4) * 4);
            int sz = (grow < M) ? 16 : 0;
            asm volatile("cp.async.cg.shared.global [%0], [%1], 16, %2;\n"
                         :: "r"(dst), "l"(src), "r"(sz));
        }
        // B tile: 16 rows x 128 cols = 512 float4, 2 per thread
#pragma unroll
        for (int i = 0; i < 2; i++) {
            int lin = t + i * 256;
            int kr = lin >> 5, q = lin & 31;
            const float* src = Bmat + (size_t)(k0 + kr) * F_H + q * 4;
            uint32_t dst = sB_u + (uint32_t)((stg * BS_STAGE + kr * BS_STRIDE + q * 4) * 4);
            asm volatile("cp.async.cg.shared.global [%0], [%1], 16, 16;\n"
                         :: "r"(dst), "l"(src));
        }
        asm volatile("cp.async.commit_group;\n");
    };

    loadStage(0, 0);

    for (int it = 0; it < NIT; ++it) {
        const int stg = it & 1;
        if (it + 1 < NIT) {
            loadStage(it + 1, stg ^ 1);
            asm volatile("cp.async.wait_group 1;\n");
        } else {
            asm volatile("cp.async.wait_group 0;\n");
        }
        __syncthreads();

        const float* A_ = sA + stg * AS_STAGE;
        const float* B_ = sB + stg * BS_STAGE;

#pragma unroll
        for (int ka = 0; ka < 2; ka++) {
            const int kb = ka * 8;
            uint32_t a[4][4], b[4][2];
#pragma unroll
            for (int ma = 0; ma < 4; ma++) {
                int m = wm + ma * 16 + g;
                a[ma][0] = f2tf(A_[m * AS_STRIDE + kb + t4]);
                a[ma][1] = f2tf(A_[(m + 8) * AS_STRIDE + kb + t4]);
                a[ma][2] = f2tf(A_[m * AS_STRIDE + kb + t4 + 4]);
                a[ma][3] = f2tf(A_[(m + 8) * AS_STRIDE + kb + t4 + 4]);
            }
#pragma unroll
            for (int nb = 0; nb < 4; nb++) {
                int n = wn + nb * 8 + g;
                b[nb][0] = f2tf(B_[(kb + t4) * BS_STRIDE + n]);
                b[nb][1] = f2tf(B_[(kb + t4 + 4) * BS_STRIDE + n]);
            }
#pragma unroll
            for (int ma = 0; ma < 4; ma++)
#pragma unroll
                for (int nb = 0; nb < 4; nb++)
                    mma_tf32(acc[ma][nb], a[ma], b[nb]);
        }
        __syncthreads();
    }

    // Epilogue
    float* __restrict__ out = isRes ? out_res : out_msg;
#pragma unroll
    for (int nb = 0; nb < 4; nb++) {
        const int col = wn + nb * 8 + 2 * t4;
        float2 brv = make_float2(0.f, 0.f);
        if (isRes) { brv.x = br[col]; brv.y = br[col + 1]; }
#pragma unroll
        for (int ma = 0; ma < 4; ma++) {
            int row0 = bm + wm + ma * 16 + g;
            float2 v0, v1;
            v0.x = acc[ma][nb][0]; v0.y = acc[ma][nb][1];
            v1.x = acc[ma][nb][2]; v1.y = acc[ma][nb][3];
            if (isRes) {
                v0.x = fmaxf(v0.x + brv.x, 0.f); v0.y = fmaxf(v0.y + brv.y, 0.f);
                v1.x = fmaxf(v1.x + brv.x, 0.f); v1.y = fmaxf(v1.y + brv.y, 0.f);
            }
            if (row0 < M)
                *(float2*)(out + (size_t)row0 * F_H + col) = v0;
            if (row0 + 8 < M)
                *(float2*)(out + (size_t)(row0 + 8) * F_H + col) = v1;
        }
    }
}

// ---------------------------------------------------------------------------
__global__ void zero_kernel(float4* __restrict__ p, int n4)
{
    int i = blockIdx.x * blockDim.x + threadIdx.x;
    if (i < n4) p[i] = make_float4(0.f, 0.f, 0.f, 0.f);
}

// Edge scatter: one warp per edge, lane handles 4 floats.
__global__ void scatter_kernel(const float* __restrict__ msg, float* __restrict__ agg,
                               const int* __restrict__ src, const int* __restrict__ dst,
                               int E)
{
    int tid  = blockIdx.x * blockDim.x + threadIdx.x;
    int e    = tid >> 5;
    int lane = tid & 31;
    if (e >= E) return;
    int s = __ldg(src + e);
    int d = __ldg(dst + e);
    float4 v = *(const float4*)(msg + (size_t)s * F_H + lane * 4);
    float* p = agg + (size_t)d * F_H + lane * 4;
    asm volatile("red.global.add.v4.f32 [%0], {%1,%2,%3,%4};"
                 :: "l"(p), "f"(v.x), "f"(v.y), "f"(v.z), "f"(v.w)
                 : "memory");
}

// h = BN( relu(agg + b) + res_with_relu ) — fully float4-vectorized
__global__ void post_kernel(const float4* __restrict__ agg, const float4* __restrict__ res,
                            const float4* __restrict__ b, const float4* __restrict__ gamma,
                            const float4* __restrict__ beta, const float4* __restrict__ mean,
                            const float4* __restrict__ var, float4* __restrict__ hout, int n4)
{
    int idx = blockIdx.x * blockDim.x + threadIdx.x;
    if (idx >= n4) return;
    int c = idx & 31;  // float4-column 0..31
    float4 a = agg[idx];
    float4 r = res[idx];
    float4 bb = __ldg(b + c);
    float4 gm = __ldg(gamma + c);
    float4 be = __ldg(beta + c);
    float4 mn = __ldg(mean + c);
    float4 vr = __ldg(var + c);
    float4 o;
    o.x = (fmaxf(a.x + bb.x, 0.f) + r.x - mn.x) * rsqrtf(vr.x + EPS) * gm.x + be.x;
    o.y = (fmaxf(a.y + bb.y, 0.f) + r.y - mn.y) * rsqrtf(vr.y + EPS) * gm.y + be.y;
    o.z = (fmaxf(a.z + bb.z, 0.f) + r.z - mn.z) * rsqrtf(vr.z + EPS) * gm.z + be.z;
    o.w = (fmaxf(a.w + bb.w, 0.f) + r.w - mn.w) * rsqrtf(vr.w + EPS) * gm.w + be.w;
    hout[idx] = o;
}

// out = softmax(h @ Wd + bd), one warp per node
__global__ void head_kernel(const float* __restrict__ h, const float* __restrict__ Wd,
                            const float* __restrict__ bd, float* __restrict__ out, int N)
{
    __shared__ float wd[F_H * 2];
    int t = threadIdx.x;
    wd[t] = Wd[t];   // blockDim == 256 == F_H*2
    __syncthreads();

    int gwarp = (blockIdx.x * blockDim.x + t) >> 5;
    int lane  = t & 31;
    if (gwarp >= N) return;

    float4 v = *(const float4*)(h + (size_t)gwarp * F_H + lane * 4);
    int k = lane * 4;
    float l0 = v.x * wd[(k + 0) * 2] + v.y * wd[(k + 1) * 2] +
               v.z * wd[(k + 2) * 2] + v.w * wd[(k + 3) * 2];
    float l1 = v.x * wd[(k + 0) * 2 + 1] + v.y * wd[(k + 1) * 2 + 1] +
               v.z * wd[(k + 2) * 2 + 1] + v.w * wd[(k + 3) * 2 + 1];
#pragma unroll
    for (int off = 16; off > 0; off >>= 1) {
        l0 += __shfl_xor_sync(0xFFFFFFFFu, l0, off);
        l1 += __shfl_xor_sync(0xFFFFFFFFu, l1, off);
    }
    if (lane == 0) {
        l0 += __ldg(bd + 0);
        l1 += __ldg(bd + 1);
        float m  = fmaxf(l0, l1);
        float e0 = __expf(l0 - m), e1 = __expf(l1 - m);
        float inv = 1.f / (e0 + e1);
        out[(size_t)gwarp * 2 + 0] = e0 * inv;
        out[(size_t)gwarp * 2 + 1] = e1 * inv;
    }
}

// ---------------------------------------------------------------------------
extern "C" void kernel_launch(void* const* d_in, const int* in_sizes, int n_in,
                              void* d_out, int out_size)
{
    const float* in_feat = (const float*)d_in[0];
    const int*   src     = (const int*)d_in[1];
    const int*   dst     = (const int*)d_in[2];
    const float* W0   = (const float*)d_in[3];
    const float* b0   = (const float*)d_in[4];
    const float* Wr0  = (const float*)d_in[5];
    const float* br0  = (const float*)d_in[6];
    const float* g0   = (const float*)d_in[7];
    const float* be0  = (const float*)d_in[8];
    const float* m0   = (const float*)d_in[9];
    const float* v0   = (const float*)d_in[10];
    const float* W1   = (const float*)d_in[11];
    const float* b1   = (const float*)d_in[12];
    const float* Wr1  = (const float*)d_in[13];
    const float* br1  = (const float*)d_in[14];
    const float* g1   = (const float*)d_in[15];
    const float* be1  = (const float*)d_in[16];
    const float* m1   = (const float*)d_in[17];
    const float* v1   = (const float*)d_in[18];
    const float* Wd   = (const float*)d_in[19];
    const float* bd   = (const float*)d_in[20];

    const int N = in_sizes[0] / F_IN;   // 50000
    const int E = in_sizes[1];          // 800000

    static float *pA = nullptr, *pB = nullptr, *pC = nullptr, *pD = nullptr;
    if (pA == nullptr) {
        cudaGetSymbolAddress((void**)&pA, g_bufA);
        cudaGetSymbolAddress((void**)&pB, g_bufB);
        cudaGetSymbolAddress((void**)&pC, g_bufC);
        cudaGetSymbolAddress((void**)&pD, g_bufD);
    }

    const dim3 gemm_grid(2, (N + 127) / 128);
    const int  n4 = N * (F_H / 4);
    const int  zb = (n4 + 255) / 256;
    const int  sb = (int)(((int64_t)E * 32 + 255) / 256);
    const int  pb = (n4 + 255) / 256;
    const int  hb = (N + 7) / 8;

    // ----- Layer 0 -----
    gemm_tf32_kernel<F_IN><<<gemm_grid, 256>>>(in_feat, W0, Wr0, br0, pA, pB, N);
    zero_kernel<<<zb, 256>>>((float4*)pC, n4);
    scatter_kernel<<<sb, 256>>>(pA, pC, src, dst, E);
    post_kernel<<<pb, 256>>>((const float4*)pC, (const float4*)pB, (const float4*)b0,
                             (const float4*)g0, (const float4*)be0, (const float4*)m0,
                             (const float4*)v0, (float4*)pA, n4);   // h1 -> A

    // ----- Layer 1 -----
    gemm_tf32_kernel<F_H><<<gemm_grid, 256>>>(pA, W1, Wr1, br1, pB, pD, N);
    zero_kernel<<<zb, 256>>>((float4*)pC, n4);
    scatter_kernel<<<sb, 256>>>(pB, pC, src, dst, E);
    post_kernel<<<pb, 256>>>((const float4*)pC, (const float4*)pD, (const float4*)b1,
                             (const float4*)g1, (const float4*)be1, (const float4*)m1,
                             (const float4*)v1, (float4*)pA, n4);   // h2 -> A

    // ----- Head -----
    head_kernel<<<hb, 256>>>(pA, Wd, bd, (float*)d_out, N);
}

// round 3
// speedup vs baseline: 3.6974x; 1.1095x over previous
#include <cuda_runtime.h>
#include <cuda_bf16.h>
#include <cstdint>

#define F_IN  1024
#define F_H   128
#define EPS   1e-5f
#define NODES_MAX 50048
#define EDGES_MAX 800000

// ------------------------- scratch (__device__ globals) ---------------------
__device__ __align__(256) float g_msg[NODES_MAX * F_H];
__device__ __align__(256) float g_res[NODES_MAX * F_H];
__device__ __align__(256) __nv_bfloat16 g_Xbf[NODES_MAX * F_IN];
__device__ __align__(256) __nv_bfloat16 g_Hbf[NODES_MAX * F_H];
__device__ __align__(256) __nv_bfloat16 g_W0t [F_H * F_IN];
__device__ __align__(256) __nv_bfloat16 g_Wr0t[F_H * F_IN];
__device__ __align__(256) __nv_bfloat16 g_W1t [F_H * F_H];
__device__ __align__(256) __nv_bfloat16 g_Wr1t[F_H * F_H];
__device__ int g_deg [NODES_MAX];
__device__ int g_row [NODES_MAX];
__device__ int g_cur [NODES_MAX];
__device__ int g_esrc[EDGES_MAX];
__device__ int g_bsum[256];

// ------------------------- conversion kernels -------------------------------
__global__ void convX_kernel(const float4* __restrict__ x, __nv_bfloat162* __restrict__ o, int n4)
{
    int i = blockIdx.x * blockDim.x + threadIdx.x;
    if (i >= n4) return;
    float4 v = x[i];
    __nv_bfloat162 p0, p1;
    p0.x = __float2bfloat16(v.x); p0.y = __float2bfloat16(v.y);
    p1.x = __float2bfloat16(v.z); p1.y = __float2bfloat16(v.w);
    o[(size_t)i * 2]     = p0;
    o[(size_t)i * 2 + 1] = p1;
}

// W [K][128] fp32 -> Wt [128][K] bf16 (transposed so k is contiguous)
__global__ void convW_kernel(const float* __restrict__ w, __nv_bfloat16* __restrict__ wt, int K)
{
    int idx = blockIdx.x * blockDim.x + threadIdx.x;
    if (idx >= K * F_H) return;
    int k = idx >> 7, n = idx & 127;
    wt[(size_t)n * K + k] = __float2bfloat16(w[idx]);
}

// ------------------------- CSR build ----------------------------------------
__global__ void zerodeg_kernel(int N)
{
    int i = blockIdx.x * blockDim.x + threadIdx.x;
    if (i < N) g_deg[i] = 0;
}
__global__ void hist_kernel(const int* __restrict__ dst, int E)
{
    int e = blockIdx.x * blockDim.x + threadIdx.x;
    if (e < E) atomicAdd(&g_deg[dst[e]], 1);
}
__global__ void scan1_kernel(int N)
{
    __shared__ int s[256];
    int t = threadIdx.x;
    int i = blockIdx.x * 256 + t;
    int v = (i < N) ? g_deg[i] : 0;
    s[t] = v;
    __syncthreads();
#pragma unroll
    for (int off = 1; off < 256; off <<= 1) {
        int x = (t >= off) ? s[t - off] : 0;
        __syncthreads();
        s[t] += x;
        __syncthreads();
    }
    if (i < N) g_row[i] = s[t] - v;           // exclusive within block
    if (t == 255) g_bsum[blockIdx.x] = s[255];
}
__global__ void scan2_kernel(int NB)
{
    __shared__ int s[256];
    int t = threadIdx.x;
    int v = (t < NB) ? g_bsum[t] : 0;
    s[t] = v;
    __syncthreads();
#pragma unroll
    for (int off = 1; off < 256; off <<= 1) {
        int x = (t >= off) ? s[t - off] : 0;
        __syncthreads();
        s[t] += x;
        __syncthreads();
    }
    if (t < NB) g_bsum[t] = s[t] - v;          // exclusive
}
__global__ void scan3_kernel(int N)
{
    int i = blockIdx.x * blockDim.x + threadIdx.x;
    if (i >= N) return;
    int r = g_row[i] + g_bsum[blockIdx.x];
    g_row[i] = r;
    g_cur[i] = r;
}
__global__ void fill_kernel(const int* __restrict__ src, const int* __restrict__ dst, int E)
{
    int e = blockIdx.x * blockDim.x + threadIdx.x;
    if (e >= E) return;
    int d = dst[e];
    int pos = atomicAdd(&g_cur[d], 1);
    g_esrc[pos] = src[e];
}

// ------------------------- bf16 tensor-core dual GEMM -----------------------
// blockIdx.x: 0 -> out_msg = X @ W (raw); 1 -> out_res = relu(X @ Wr + br)
// blockIdx.y: M tile (BM=128). BN=128 covers all output cols.
// 256 thr, 8 warps 2(M)x4(N), warp tile 64x32, mma m16n8k16 bf16, ldmatrix A.
__device__ __forceinline__ void mma_bf16(float* c, const uint32_t* a, const uint32_t* b)
{
    asm volatile(
        "mma.sync.aligned.m16n8k16.row.col.f32.bf16.bf16.f32 "
        "{%0,%1,%2,%3}, {%4,%5,%6,%7}, {%8,%9}, {%0,%1,%2,%3};"
        : "+f"(c[0]), "+f"(c[1]), "+f"(c[2]), "+f"(c[3])
        : "r"(a[0]), "r"(a[1]), "r"(a[2]), "r"(a[3]), "r"(b[0]), "r"(b[1]));
}

template <int KD>
__global__ void __launch_bounds__(256, 2) gemm_bf16_kernel(
    const __nv_bfloat16* __restrict__ Xb, const __nv_bfloat16* __restrict__ Wt,
    const __nv_bfloat16* __restrict__ Wrt, const float* __restrict__ br,
    float* __restrict__ out_msg, float* __restrict__ out_res, int M)
{
    constexpr int BM = 128, BN = 128, BK = 32;
    constexpr int NIT = KD / BK;
    constexpr int SA = 40;                 // bf16 stride (32 + 8 pad = 80B rows)
    constexpr int SB = 40;
    constexpr int AS_STAGE = BM * SA;
    constexpr int BS_STAGE = BN * SB;

    __shared__ __align__(16) __nv_bfloat16 sA[2 * AS_STAGE];
    __shared__ __align__(16) __nv_bfloat16 sB[2 * BS_STAGE];

    const int t = threadIdx.x;
    const bool isRes = (blockIdx.x == 1);
    const __nv_bfloat16* __restrict__ Bmat = isRes ? Wrt : Wt;
    const int bm = blockIdx.y * BM;

    const int lane = t & 31;
    const int w    = t >> 5;
    const int wm   = (w & 1) * 64;
    const int wn   = (w >> 1) * 32;
    const int g    = lane >> 2;
    const int t4   = lane & 3;

    const uint32_t sA_u = (uint32_t)__cvta_generic_to_shared(sA);

    float acc[4][4][4];
#pragma unroll
    for (int i = 0; i < 4; i++)
#pragma unroll
        for (int j = 0; j < 4; j++)
#pragma unroll
            for (int k = 0; k < 4; k++) acc[i][j][k] = 0.f;

    const uint32_t sB_u = (uint32_t)__cvta_generic_to_shared(sB);

    auto loadStage = [&](int it, int stg) {
        const int k0 = it * BK;
        // A tile: 128 rows x 32 bf16 = 128x4 16B chunks = 512, 2/thread
#pragma unroll
        for (int i = 0; i < 2; i++) {
            int lin = t + i * 256;
            int m = lin >> 2, q = lin & 3;
            int grow = bm + m;
            const __nv_bfloat16* src = Xb + (size_t)grow * KD + k0 + q * 8;
            uint32_t d = sA_u + (uint32_t)((stg * AS_STAGE + m * SA + q * 8) * 2);
            int sz = (grow < M) ? 16 : 0;
            asm volatile("cp.async.cg.shared.global [%0], [%1], 16, %2;\n"
                         :: "r"(d), "l"(src), "r"(sz));
        }
        // B tile: 128 n-rows x 32 bf16 = 512 chunks, 2/thread
#pragma unroll
        for (int i = 0; i < 2; i++) {
            int lin = t + i * 256;
            int n = lin >> 2, q = lin & 3;
            const __nv_bfloat16* src = Bmat + (size_t)n * KD + k0 + q * 8;
            uint32_t d = sB_u + (uint32_t)((stg * BS_STAGE + n * SB + q * 8) * 2);
            asm volatile("cp.async.cg.shared.global [%0], [%1], 16, 16;\n"
                         :: "r"(d), "l"(src));
        }
        asm volatile("cp.async.commit_group;\n");
    };

    loadStage(0, 0);

    const int mrow = lane & 15;
    const int ksel = (lane >> 4) * 8;

    for (int it = 0; it < NIT; ++it) {
        const int stg = it & 1;
        if (it + 1 < NIT) {
            loadStage(it + 1, stg ^ 1);
            asm volatile("cp.async.wait_group 1;\n");
        } else {
            asm volatile("cp.async.wait_group 0;\n");
        }
        __syncthreads();

        const __nv_bfloat16* B_ = sB + stg * BS_STAGE;
        const uint32_t A_u = sA_u + (uint32_t)(stg * AS_STAGE * 2);

#pragma unroll
        for (int ks = 0; ks < 2; ks++) {
            const int kb = ks * 16;
            uint32_t a[4][4], b[4][2];
#pragma unroll
            for (int ma = 0; ma < 4; ma++) {
                uint32_t addr = A_u + (uint32_t)(((wm + ma * 16 + mrow) * SA + kb + ksel) * 2);
                asm volatile("ldmatrix.sync.aligned.m8n8.x4.shared.b16 {%0,%1,%2,%3}, [%4];"
                             : "=r"(a[ma][0]), "=r"(a[ma][1]), "=r"(a[ma][2]), "=r"(a[ma][3])
                             : "r"(addr));
            }
#pragma unroll
            for (int nb = 0; nb < 4; nb++) {
                int n = wn + nb * 8 + g;
                const __nv_bfloat16* p = B_ + n * SB + kb + t4 * 2;
                b[nb][0] = *(const uint32_t*)p;
                b[nb][1] = *(const uint32_t*)(p + 8);
            }
#pragma unroll
            for (int ma = 0; ma < 4; ma++)
#pragma unroll
                for (int nb = 0; nb < 4; nb++)
                    mma_bf16(acc[ma][nb], a[ma], b[nb]);
        }
        __syncthreads();
    }

    // Epilogue
    float* __restrict__ out = isRes ? out_res : out_msg;
#pragma unroll
    for (int nb = 0; nb < 4; nb++) {
        const int col = wn + nb * 8 + 2 * t4;
        float2 brv = make_float2(0.f, 0.f);
        if (isRes) { brv.x = br[col]; brv.y = br[col + 1]; }
#pragma unroll
        for (int ma = 0; ma < 4; ma++) {
            int row0 = bm + wm + ma * 16 + g;
            float2 v0, v1;
            v0.x = acc[ma][nb][0]; v0.y = acc[ma][nb][1];
            v1.x = acc[ma][nb][2]; v1.y = acc[ma][nb][3];
            if (isRes) {
                v0.x = fmaxf(v0.x + brv.x, 0.f); v0.y = fmaxf(v0.y + brv.y, 0.f);
                v1.x = fmaxf(v1.x + brv.x, 0.f); v1.y = fmaxf(v1.y + brv.y, 0.f);
            }
            if (row0 < M)
                *(float2*)(out + (size_t)row0 * F_H + col) = v0;
            if (row0 + 8 < M)
                *(float2*)(out + (size_t)(row0 + 8) * F_H + col) = v1;
        }
    }
}

// ------------------------- gather + fused epilogues -------------------------
// Layer 0: agg -> relu(+b) + res -> BN -> bf16 h1
__global__ void gather0_kernel(const float* __restrict__ msg, const float* __restrict__ res,
                               const float4* __restrict__ b4, const float4* __restrict__ g4,
                               const float4* __restrict__ be4, const float4* __restrict__ mn4,
                               const float4* __restrict__ vr4,
                               __nv_bfloat162* __restrict__ hout, int N)
{
    int wid  = (blockIdx.x * blockDim.x + threadIdx.x) >> 5;
    int lane = threadIdx.x & 31;
    if (wid >= N) return;
    int s = g_row[wid], e = g_cur[wid];

    float4 a0 = make_float4(0.f, 0.f, 0.f, 0.f);
    float4 a1 = make_float4(0.f, 0.f, 0.f, 0.f);
    int i = s;
    for (; i + 2 <= e; i += 2) {
        int u = __ldg(&g_esrc[i]), v = __ldg(&g_esrc[i + 1]);
        float4 x = *(const float4*)(msg + (size_t)u * F_H + lane * 4);
        float4 y = *(const float4*)(msg + (size_t)v * F_H + lane * 4);
        a0.x += x.x; a0.y += x.y; a0.z += x.z; a0.w += x.w;
        a1.x += y.x; a1.y += y.y; a1.z += y.z; a1.w += y.w;
    }
    if (i < e) {
        int u = __ldg(&g_esrc[i]);
        float4 x = *(const float4*)(msg + (size_t)u * F_H + lane * 4);
        a0.x += x.x; a0.y += x.y; a0.z += x.z; a0.w += x.w;
    }
    a0.x += a1.x; a0.y += a1.y; a0.z += a1.z; a0.w += a1.w;

    float4 r  = *(const float4*)(res + (size_t)wid * F_H + lane * 4);
    float4 bb = __ldg(b4 + lane);
    float4 gm = __ldg(g4 + lane);
    float4 be = __ldg(be4 + lane);
    float4 mn = __ldg(mn4 + lane);
    float4 vr = __ldg(vr4 + lane);
    float o0 = (fmaxf(a0.x + bb.x, 0.f) + r.x - mn.x) * rsqrtf(vr.x + EPS) * gm.x + be.x;
    float o1 = (fmaxf(a0.y + bb.y, 0.f) + r.y - mn.y) * rsqrtf(vr.y + EPS) * gm.y + be.y;
    float o2 = (fmaxf(a0.z + bb.z, 0.f) + r.z - mn.z) * rsqrtf(vr.z + EPS) * gm.z + be.z;
    float o3 = (fmaxf(a0.w + bb.w, 0.f) + r.w - mn.w) * rsqrtf(vr.w + EPS) * gm.w + be.w;

    __nv_bfloat162 p0, p1;
    p0.x = __float2bfloat16(o0); p0.y = __float2bfloat16(o1);
    p1.x = __float2bfloat16(o2); p1.y = __float2bfloat16(o3);
    hout[(size_t)wid * (F_H / 2) + lane * 2]     = p0;
    hout[(size_t)wid * (F_H / 2) + lane * 2 + 1] = p1;
}

// Layer 1: agg -> relu(+b) + res -> BN -> logits -> softmax -> out[N,2]
__global__ void gather1_head_kernel(const float* __restrict__ msg, const float* __restrict__ res,
                                    const float4* __restrict__ b4, const float4* __restrict__ g4,
                                    const float4* __restrict__ be4, const float4* __restrict__ mn4,
                                    const float4* __restrict__ vr4,
                                    const float* __restrict__ Wd, const float* __restrict__ bd,
                                    float* __restrict__ out, int N)
{
    __shared__ float wd[F_H * 2];
    wd[threadIdx.x] = Wd[threadIdx.x];   // blockDim == 256
    __syncthreads();

    int wid  = (blockIdx.x * blockDim.x + threadIdx.x) >> 5;
    int lane = threadIdx.x & 31;
    if (wid >= N) return;
    int s = g_row[wid], e = g_cur[wid];

    float4 a0 = make_float4(0.f, 0.f, 0.f, 0.f);
    float4 a1 = make_float4(0.f, 0.f, 0.f, 0.f);
    int i = s;
    for (; i + 2 <= e; i += 2) {
        int u = __ldg(&g_esrc[i]), v = __ldg(&g_esrc[i + 1]);
        float4 x = *(const float4*)(msg + (size_t)u * F_H + lane * 4);
        float4 y = *(const float4*)(msg + (size_t)v * F_H + lane * 4);
        a0.x += x.x; a0.y += x.y; a0.z += x.z; a0.w += x.w;
        a1.x += y.x; a1.y += y.y; a1.z += y.z; a1.w += y.w;
    }
    if (i < e) {
        int u = __ldg(&g_esrc[i]);
        float4 x = *(const float4*)(msg + (size_t)u * F_H + lane * 4);
        a0.x += x.x; a0.y += x.y; a0.z += x.z; a0.w += x.w;
    }
    a0.x += a1.x; a0.y += a1.y; a0.z += a1.z; a0.w += a1.w;

    float4 r  = *(const float4*)(res + (size_t)wid * F_H + lane * 4);
    float4 bb = __ldg(b4 + lane);
    float4 gm = __ldg(g4 + lane);
    float4 be = __ldg(be4 + lane);
    float4 mn = __ldg(mn4 + lane);
    float4 vr = __ldg(vr4 + lane);
    float h0 = (fmaxf(a0.x + bb.x, 0.f) + r.x - mn.x) * rsqrtf(vr.x + EPS) * gm.x + be.x;
    float h1 = (fmaxf(a0.y + bb.y, 0.f) + r.y - mn.y) * rsqrtf(vr.y + EPS) * gm.y + be.y;
    float h2 = (fmaxf(a0.z + bb.z, 0.f) + r.z - mn.z) * rsqrtf(vr.z + EPS) * gm.z + be.z;
    float h3 = (fmaxf(a0.w + bb.w, 0.f) + r.w - mn.w) * rsqrtf(vr.w + EPS) * gm.w + be.w;

    int c = lane * 4;
    float l0 = h0 * wd[(c + 0) * 2] + h1 * wd[(c + 1) * 2] +
               h2 * wd[(c + 2) * 2] + h3 * wd[(c + 3) * 2];
    float l1 = h0 * wd[(c + 0) * 2 + 1] + h1 * wd[(c + 1) * 2 + 1] +
               h2 * wd[(c + 2) * 2 + 1] + h3 * wd[(c + 3) * 2 + 1];
#pragma unroll
    for (int off = 16; off > 0; off >>= 1) {
        l0 += __shfl_xor_sync(0xFFFFFFFFu, l0, off);
        l1 += __shfl_xor_sync(0xFFFFFFFFu, l1, off);
    }
    if (lane == 0) {
        l0 += __ldg(bd + 0);
        l1 += __ldg(bd + 1);
        float m  = fmaxf(l0, l1);
        float e0 = __expf(l0 - m), e1 = __expf(l1 - m);
        float inv = 1.f / (e0 + e1);
        out[(size_t)wid * 2 + 0] = e0 * inv;
        out[(size_t)wid * 2 + 1] = e1 * inv;
    }
}

// ---------------------------------------------------------------------------
extern "C" void kernel_launch(void* const* d_in, const int* in_sizes, int n_in,
                              void* d_out, int out_size)
{
    const float* in_feat = (const float*)d_in[0];
    const int*   src     = (const int*)d_in[1];
    const int*   dst     = (const int*)d_in[2];
    const float* W0   = (const float*)d_in[3];
    const float* b0   = (const float*)d_in[4];
    const float* Wr0  = (const float*)d_in[5];
    const float* br0  = (const float*)d_in[6];
    const float* g0   = (const float*)d_in[7];
    const float* be0  = (const float*)d_in[8];
    const float* m0   = (const float*)d_in[9];
    const float* v0   = (const float*)d_in[10];
    const float* W1   = (const float*)d_in[11];
    const float* b1   = (const float*)d_in[12];
    const float* Wr1  = (const float*)d_in[13];
    const float* br1  = (const float*)d_in[14];
    const float* g1   = (const float*)d_in[15];
    const float* be1  = (const float*)d_in[16];
    const float* m1   = (const float*)d_in[17];
    const float* v1   = (const float*)d_in[18];
    const float* Wd   = (const float*)d_in[19];
    const float* bd   = (const float*)d_in[20];

    const int N = in_sizes[0] / F_IN;   // 50000
    const int E = in_sizes[1];          // 800000

    struct Ptrs {
        float *msg, *res; __nv_bfloat16 *xbf, *hbf, *w0t, *wr0t, *w1t, *wr1t;
        int *deg, *row, *cur, *esrc, *bsum;
    };
    static Ptrs P = {};
    if (P.msg == nullptr) {
        cudaGetSymbolAddress((void**)&P.msg,  g_msg);
        cudaGetSymbolAddress((void**)&P.res,  g_res);
        cudaGetSymbolAddress((void**)&P.xbf,  g_Xbf);
        cudaGetSymbolAddress((void**)&P.hbf,  g_Hbf);
        cudaGetSymbolAddress((void**)&P.w0t,  g_W0t);
        cudaGetSymbolAddress((void**)&P.wr0t, g_Wr0t);
        cudaGetSymbolAddress((void**)&P.w1t,  g_W1t);
        cudaGetSymbolAddress((void**)&P.wr1t, g_Wr1t);
    }

    const int NB   = (N + 255) / 256;                 // scan blocks (196 <= 256)
    const int eb   = (E + 255) / 256;
    const int x4   = N * (F_IN / 4);
    const int gb   = (N + 7) / 8;                     // gather: 8 warps/block
    const dim3 gemm_grid(2, (N + 127) / 128);

    // conversions
    convX_kernel<<<(x4 + 255) / 256, 256>>>((const float4*)in_feat, (__nv_bfloat162*)P.xbf, x4);
    convW_kernel<<<(F_IN * F_H + 255) / 256, 256>>>(W0,  P.w0t,  F_IN);
    convW_kernel<<<(F_IN * F_H + 255) / 256, 256>>>(Wr0, P.wr0t, F_IN);
    convW_kernel<<<(F_H * F_H + 255) / 256, 256>>>(W1,  P.w1t,  F_H);
    convW_kernel<<<(F_H * F_H + 255) / 256, 256>>>(Wr1, P.wr1t, F_H);

    // CSR build (shared by both layers)
    zerodeg_kernel<<<NB, 256>>>(N);
    hist_kernel<<<eb, 256>>>(dst, E);
    scan1_kernel<<<NB, 256>>>(N);
    scan2_kernel<<<1, 256>>>(NB);
    scan3_kernel<<<NB, 256>>>(N);
    fill_kernel<<<eb, 256>>>(src, dst, E);

    // Layer 0
    gemm_bf16_kernel<F_IN><<<gemm_grid, 256>>>(P.xbf, P.w0t, P.wr0t, br0, P.msg, P.res, N);
    gather0_kernel<<<gb, 256>>>(P.msg, P.res, (const float4*)b0, (const float4*)g0,
                                (const float4*)be0, (const float4*)m0, (const float4*)v0,
                                (__nv_bfloat162*)P.hbf, N);

    // Layer 1
    gemm_bf16_kernel<F_H><<<gemm_grid, 256>>>(P.hbf, P.w1t, P.wr1t, br1, P.msg, P.res, N);
    gather1_head_kernel<<<gb, 256>>>(P.msg, P.res, (const float4*)b1, (const float4*)g1,
                                     (const float4*)be1, (const float4*)m1, (const float4*)v1,
                                     Wd, bd, (float*)d_out, N);
}

// round 5
// speedup vs baseline: 5.5002x; 1.4876x over previous
#include <cuda_runtime.h>
#include <cuda_bf16.h>
#include <cstdint>

#define F_IN  1024
#define F_H   128
#define EPS   1e-5f
#define NODES_MAX 50048
#define EDGES_MAX 800000

// ------------------------- scratch (__device__ globals) ---------------------
__device__ __align__(256) __nv_bfloat16 g_msg[NODES_MAX * F_H];
__device__ __align__(256) __nv_bfloat16 g_res[NODES_MAX * F_H];
__device__ __align__(256) __nv_bfloat16 g_Xbf[NODES_MAX * F_IN];
__device__ __align__(256) __nv_bfloat16 g_Hbf[NODES_MAX * F_H];
__device__ __align__(256) __nv_bfloat16 g_W0t [F_H * F_IN];
__device__ __align__(256) __nv_bfloat16 g_Wr0t[F_H * F_IN];
__device__ __align__(256) __nv_bfloat16 g_W1t [F_H * F_H];
__device__ __align__(256) __nv_bfloat16 g_Wr1t[F_H * F_H];
__device__ int g_deg [NODES_MAX];
__device__ int g_row [NODES_MAX];
__device__ int g_cur [NODES_MAX];
__device__ int g_esrc[EDGES_MAX];
__device__ int g_bsum[256];

// ------------------------- fused conversion ---------------------------------
// Block ranges: [0, XB)                : X fp32 -> bf16 (float4 granularity)
//               [XB, XB+512)           : W0  -> W0t  (transpose, K=1024)
//               [XB+512, XB+1024)      : Wr0 -> Wr0t
//               [XB+1024, XB+1088)     : W1  -> W1t  (K=128)
//               [XB+1088, XB+1152)     : Wr1 -> Wr1t
__global__ void convAll_kernel(const float4* __restrict__ x, __nv_bfloat162* __restrict__ xo,
                               int n4, int XB,
                               const float* __restrict__ W0,  __nv_bfloat16* __restrict__ W0t,
                               const float* __restrict__ Wr0, __nv_bfloat16* __restrict__ Wr0t,
                               const float* __restrict__ W1,  __nv_bfloat16* __restrict__ W1t,
                               const float* __restrict__ Wr1, __nv_bfloat16* __restrict__ Wr1t)
{
    int b = blockIdx.x;
    if (b < XB) {
        int i = b * 256 + threadIdx.x;
        if (i >= n4) return;
        float4 v = x[i];
        __nv_bfloat162 p0, p1;
        p0.x = __float2bfloat16(v.x); p0.y = __float2bfloat16(v.y);
        p1.x = __float2bfloat16(v.z); p1.y = __float2bfloat16(v.w);
        xo[(size_t)i * 2]     = p0;
        xo[(size_t)i * 2 + 1] = p1;
        return;
    }
    b -= XB;
    const float* w; __nv_bfloat16* wt; int K;
    if (b < 512)        { w = W0;  wt = W0t;  K = F_IN; }
    else if (b < 1024)  { w = Wr0; wt = Wr0t; K = F_IN; b -= 512; }
    else if (b < 1088)  { w = W1;  wt = W1t;  K = F_H;  b -= 1024; }
    else                { w = Wr1; wt = Wr1t; K = F_H;  b -= 1088; }
    int idx = b * 256 + threadIdx.x;
    if (idx >= K * F_H) return;
    int k = idx >> 7, n = idx & 127;
    wt[(size_t)n * K + k] = __float2bfloat16(w[idx]);
}

// ------------------------- CSR build ----------------------------------------
__global__ void zerodeg_kernel(int N)
{
    int i = blockIdx.x * blockDim.x + threadIdx.x;
    if (i < N) g_deg[i] = 0;
}
__global__ void hist_kernel(const int* __restrict__ dst, int E)
{
    int e = blockIdx.x * blockDim.x + threadIdx.x;
    if (e < E) atomicAdd(&g_deg[dst[e]], 1);
}
__global__ void scan1_kernel(int N)
{
    __shared__ int s[256];
    int t = threadIdx.x;
    int i = blockIdx.x * 256 + t;
    int v = (i < N) ? g_deg[i] : 0;
    s[t] = v;
    __syncthreads();
#pragma unroll
    for (int off = 1; off < 256; off <<= 1) {
        int x = (t >= off) ? s[t - off] : 0;
        __syncthreads();
        s[t] += x;
        __syncthreads();
    }
    if (i < N) g_row[i] = s[t] - v;
    if (t == 255) g_bsum[blockIdx.x] = s[255];
}
__global__ void scan2_kernel(int NB)
{
    __shared__ int s[256];
    int t = threadIdx.x;
    int v = (t < NB) ? g_bsum[t] : 0;
    s[t] = v;
    __syncthreads();
#pragma unroll
    for (int off = 1; off < 256; off <<= 1) {
        int x = (t >= off) ? s[t - off] : 0;
        __syncthreads();
        s[t] += x;
        __syncthreads();
    }
    if (t < NB) g_bsum[t] = s[t] - v;
}
__global__ void scan3_kernel(int N)
{
    int i = blockIdx.x * blockDim.x + threadIdx.x;
    if (i >= N) return;
    int r = g_row[i] + g_bsum[blockIdx.x];
    g_row[i] = r;
    g_cur[i] = r;
}
__global__ void fill_kernel(const int* __restrict__ src, const int* __restrict__ dst, int E)
{
    int e = blockIdx.x * blockDim.x + threadIdx.x;
    if (e >= E) return;
    int d = dst[e];
    int pos = atomicAdd(&g_cur[d], 1);
    g_esrc[pos] = src[e];
}

// ------------------------- bf16 single-pass dual GEMM -----------------------
// One CTA: 128 M-rows, BOTH outputs (msg = X@W raw; res = relu(X@Wr+br)),
// bf16 outputs. 256 thr, 8 warps 2(M)x4(N), warp tile 64x32 per output.
// A fragments shared across both B operands; ldmatrix for A and B.
__device__ __forceinline__ void mma_bf16(float* c, const uint32_t* a, const uint32_t* b)
{
    asm volatile(
        "mma.sync.aligned.m16n8k16.row.col.f32.bf16.bf16.f32 "
        "{%0,%1,%2,%3}, {%4,%5,%6,%7}, {%8,%9}, {%0,%1,%2,%3};"
        : "+f"(c[0]), "+f"(c[1]), "+f"(c[2]), "+f"(c[3])
        : "r"(a[0]), "r"(a[1]), "r"(a[2]), "r"(a[3]), "r"(b[0]), "r"(b[1]));
}

template <int KD>
__global__ void __launch_bounds__(256) gemm_dual_kernel(
    const __nv_bfloat16* __restrict__ Xb, const __nv_bfloat16* __restrict__ Wt,
    const __nv_bfloat16* __restrict__ Wrt, const float* __restrict__ br,
    __nv_bfloat16* __restrict__ out_msg, __nv_bfloat16* __restrict__ out_res, int M)
{
    constexpr int BM = 128, BK = 32;
    constexpr int NIT = KD / BK;
    constexpr int SA = 40;                       // bf16 stride: 32 + 8 pad (80B rows)
    constexpr int TILE = BM * SA;                // floats.. in bf16 elems: 5120
    // layout: [A stg0][A stg1][W stg0][W stg1][R stg0][R stg1]
    extern __shared__ __align__(16) __nv_bfloat16 smem[];
    __nv_bfloat16* sA = smem;
    __nv_bfloat16* sW = smem + 2 * TILE;
    __nv_bfloat16* sR = smem + 4 * TILE;

    const int t = threadIdx.x;
    const int bm = blockIdx.x * BM;
    const int lane = t & 31;
    const int w    = t >> 5;
    const int wm   = (w & 1) * 64;
    const int wn   = (w >> 1) * 32;
    const int g    = lane >> 2;
    const int t4   = lane & 3;

    const uint32_t sA_u = (uint32_t)__cvta_generic_to_shared(sA);
    const uint32_t sW_u = (uint32_t)__cvta_generic_to_shared(sW);
    const uint32_t sR_u = (uint32_t)__cvta_generic_to_shared(sR);

    float acc[2][4][4][4];
#pragma unroll
    for (int o = 0; o < 2; o++)
#pragma unroll
        for (int i = 0; i < 4; i++)
#pragma unroll
            for (int j = 0; j < 4; j++)
#pragma unroll
                for (int k = 0; k < 4; k++) acc[o][i][j][k] = 0.f;

    auto loadStage = [&](int it, int stg) {
        const int k0 = it * BK;
        // each tile: 128 rows x 32 bf16 = 512 x 16B chunks, 2 chunks/thread/tile
#pragma unroll
        for (int i = 0; i < 2; i++) {
            int lin = t + i * 256;
            int m = lin >> 2, q = lin & 3;
            uint32_t doff = (uint32_t)((stg * TILE + m * SA + q * 8) * 2);
            const __nv_bfloat16* asrc = Xb + (size_t)(bm + m) * KD + k0 + q * 8;
            int sz = (bm + m < M) ? 16 : 0;
            asm volatile("cp.async.cg.shared.global [%0], [%1], 16, %2;\n"
                         :: "r"(sA_u + doff), "l"(asrc), "r"(sz));
            const __nv_bfloat16* wsrc = Wt + (size_t)m * KD + k0 + q * 8;
            asm volatile("cp.async.cg.shared.global [%0], [%1], 16, 16;\n"
                         :: "r"(sW_u + doff), "l"(wsrc));
            const __nv_bfloat16* rsrc = Wrt + (size_t)m * KD + k0 + q * 8;
            asm volatile("cp.async.cg.shared.global [%0], [%1], 16, 16;\n"
                         :: "r"(sR_u + doff), "l"(rsrc));
        }
        asm volatile("cp.async.commit_group;\n");
    };

    loadStage(0, 0);

    const int mrow = lane & 15;          // A ldmatrix row-in-tilepair
    const int ksel = (lane >> 4) * 8;    // A ldmatrix k half
    // B ldmatrix.x4 lane mapping: khalf = (lane>>3)&1, nhalf = (lane>>4)&1, r = lane&7
    const int b_nrow = ((lane >> 4) & 1) * 8 + (lane & 7);
    const int b_koff = ((lane >> 3) & 1) * 8;

    for (int it = 0; it < NIT; ++it) {
        const int stg = it & 1;
        if (it + 1 < NIT) {
            loadStage(it + 1, stg ^ 1);
            asm volatile("cp.async.wait_group 1;\n");
        } else {
            asm volatile("cp.async.wait_group 0;\n");
        }
        __syncthreads();

        const uint32_t A_u = sA_u + (uint32_t)(stg * TILE * 2);
        const uint32_t W_u = sW_u + (uint32_t)(stg * TILE * 2);
        const uint32_t R_u = sR_u + (uint32_t)(stg * TILE * 2);

#pragma unroll
        for (int ks = 0; ks < 2; ks++) {
            const int kb = ks * 16;
            uint32_t a[4][4];
#pragma unroll
            for (int ma = 0; ma < 4; ma++) {
                uint32_t addr = A_u + (uint32_t)(((wm + ma * 16 + mrow) * SA + kb + ksel) * 2);
                asm volatile("ldmatrix.sync.aligned.m8n8.x4.shared.b16 {%0,%1,%2,%3}, [%4];"
                             : "=r"(a[ma][0]), "=r"(a[ma][1]), "=r"(a[ma][2]), "=r"(a[ma][3])
                             : "r"(addr));
            }
#pragma unroll
            for (int o = 0; o < 2; o++) {
                const uint32_t B_u = o ? R_u : W_u;
#pragma unroll
                for (int pr = 0; pr < 2; pr++) {      // pairs of n8 tiles
                    uint32_t b0, b1, b2, b3;
                    uint32_t addr = B_u + (uint32_t)(((wn + pr * 16 + b_nrow) * SA + kb + b_koff) * 2);
                    asm volatile("ldmatrix.sync.aligned.m8n8.x4.shared.b16 {%0,%1,%2,%3}, [%4];"
                                 : "=r"(b0), "=r"(b1), "=r"(b2), "=r"(b3)
                                 : "r"(addr));
                    uint32_t bl[2] = {b0, b1};
                    uint32_t bh[2] = {b2, b3};
#pragma unroll
                    for (int ma = 0; ma < 4; ma++) {
                        mma_bf16(acc[o][ma][pr * 2],     a[ma], bl);
                        mma_bf16(acc[o][ma][pr * 2 + 1], a[ma], bh);
                    }
                }
            }
        }
        __syncthreads();
    }

    // Epilogue: bf16 outputs; res gets +br then relu
#pragma unroll
    for (int o = 0; o < 2; o++) {
        __nv_bfloat16* __restrict__ out = o ? out_res : out_msg;
#pragma unroll
        for (int nb = 0; nb < 4; nb++) {
            const int col = wn + nb * 8 + 2 * t4;
            float2 brv = make_float2(0.f, 0.f);
            if (o) { brv.x = br[col]; brv.y = br[col + 1]; }
#pragma unroll
            for (int ma = 0; ma < 4; ma++) {
                int row0 = bm + wm + ma * 16 + g;
                float* c = acc[o][ma][nb];
                float2 v0 = make_float2(c[0], c[1]);
                float2 v1 = make_float2(c[2], c[3]);
                if (o) {
                    v0.x = fmaxf(v0.x + brv.x, 0.f); v0.y = fmaxf(v0.y + brv.y, 0.f);
                    v1.x = fmaxf(v1.x + brv.x, 0.f); v1.y = fmaxf(v1.y + brv.y, 0.f);
                }
                __nv_bfloat162 p0, p1;
                p0.x = __float2bfloat16(v0.x); p0.y = __float2bfloat16(v0.y);
                p1.x = __float2bfloat16(v1.x); p1.y = __float2bfloat16(v1.y);
                if (row0 < M)
                    *(__nv_bfloat162*)(out + (size_t)row0 * F_H + col) = p0;
                if (row0 + 8 < M)
                    *(__nv_bfloat162*)(out + (size_t)(row0 + 8) * F_H + col) = p1;
            }
        }
    }
}

// ------------------------- gather + fused epilogues -------------------------
__device__ __forceinline__ void acc_row(const __nv_bfloat16* __restrict__ base,
                                        int node, int lane, float4& a)
{
    uint2 q = __ldg((const uint2*)(base + (size_t)node * F_H) + lane);
    __nv_bfloat162 x0 = *(__nv_bfloat162*)&q.x;
    __nv_bfloat162 x1 = *(__nv_bfloat162*)&q.y;
    float2 f0 = __bfloat1622float2(x0);
    float2 f1 = __bfloat1622float2(x1);
    a.x += f0.x; a.y += f0.y; a.z += f1.x; a.w += f1.y;
}

// Layer 0: agg -> relu(+b) + res -> BN -> bf16 h1
__global__ void gather0_kernel(const __nv_bfloat16* __restrict__ msg,
                               const __nv_bfloat16* __restrict__ res,
                               const float4* __restrict__ b4, const float4* __restrict__ g4,
                               const float4* __restrict__ be4, const float4* __restrict__ mn4,
                               const float4* __restrict__ vr4,
                               __nv_bfloat162* __restrict__ hout, int N)
{
    int wid  = (blockIdx.x * blockDim.x + threadIdx.x) >> 5;
    int lane = threadIdx.x & 31;
    if (wid >= N) return;
    int s = g_row[wid], e = g_cur[wid];

    float4 a0 = make_float4(0.f, 0.f, 0.f, 0.f);
    float4 a1 = make_float4(0.f, 0.f, 0.f, 0.f);
    int i = s;
    for (; i + 2 <= e; i += 2) {
        int u = __ldg(&g_esrc[i]), v = __ldg(&g_esrc[i + 1]);
        acc_row(msg, u, lane, a0);
        acc_row(msg, v, lane, a1);
    }
    if (i < e) acc_row(msg, __ldg(&g_esrc[i]), lane, a0);
    a0.x += a1.x; a0.y += a1.y; a0.z += a1.z; a0.w += a1.w;

    float4 r = make_float4(0.f, 0.f, 0.f, 0.f);
    acc_row(res, wid, lane, r);
    float4 bb = __ldg(b4 + lane);
    float4 gm = __ldg(g4 + lane);
    float4 be = __ldg(be4 + lane);
    float4 mn = __ldg(mn4 + lane);
    float4 vr = __ldg(vr4 + lane);
    float o0 = (fmaxf(a0.x + bb.x, 0.f) + r.x - mn.x) * rsqrtf(vr.x + EPS) * gm.x + be.x;
    float o1 = (fmaxf(a0.y + bb.y, 0.f) + r.y - mn.y) * rsqrtf(vr.y + EPS) * gm.y + be.y;
    float o2 = (fmaxf(a0.z + bb.z, 0.f) + r.z - mn.z) * rsqrtf(vr.z + EPS) * gm.z + be.z;
    float o3 = (fmaxf(a0.w + bb.w, 0.f) + r.w - mn.w) * rsqrtf(vr.w + EPS) * gm.w + be.w;

    __nv_bfloat162 p0, p1;
    p0.x = __float2bfloat16(o0); p0.y = __float2bfloat16(o1);
    p1.x = __float2bfloat16(o2); p1.y = __float2bfloat16(o3);
    hout[(size_t)wid * (F_H / 2) + lane * 2]     = p0;
    hout[(size_t)wid * (F_H / 2) + lane * 2 + 1] = p1;
}

// Layer 1: agg -> relu(+b) + res -> BN -> logits -> softmax -> out[N,2]
__global__ void gather1_head_kernel(const __nv_bfloat16* __restrict__ msg,
                                    const __nv_bfloat16* __restrict__ res,
                                    const float4* __restrict__ b4, const float4* __restrict__ g4,
                                    const float4* __restrict__ be4, const float4* __restrict__ mn4,
                                    const float4* __restrict__ vr4,
                                    const float* __restrict__ Wd, const float* __restrict__ bd,
                                    float* __restrict__ out, int N)
{
    __shared__ float wd[F_H * 2];
    wd[threadIdx.x] = Wd[threadIdx.x];   // blockDim == 256
    __syncthreads();

    int wid  = (blockIdx.x * blockDim.x + threadIdx.x) >> 5;
    int lane = threadIdx.x & 31;
    if (wid >= N) return;
    int s = g_row[wid], e = g_cur[wid];

    float4 a0 = make_float4(0.f, 0.f, 0.f, 0.f);
    float4 a1 = make_float4(0.f, 0.f, 0.f, 0.f);
    int i = s;
    for (; i + 2 <= e; i += 2) {
        int u = __ldg(&g_esrc[i]), v = __ldg(&g_esrc[i + 1]);
        acc_row(msg, u, lane, a0);
        acc_row(msg, v, lane, a1);
    }
    if (i < e) acc_row(msg, __ldg(&g_esrc[i]), lane, a0);
    a0.x += a1.x; a0.y += a1.y; a0.z += a1.z; a0.w += a1.w;

    float4 r = make_float4(0.f, 0.f, 0.f, 0.f);
    acc_row(res, wid, lane, r);
    float4 bb = __ldg(b4 + lane);
    float4 gm = __ldg(g4 + lane);
    float4 be = __ldg(be4 + lane);
    float4 mn = __ldg(mn4 + lane);
    float4 vr = __ldg(vr4 + lane);
    float h0 = (fmaxf(a0.x + bb.x, 0.f) + r.x - mn.x) * rsqrtf(vr.x + EPS) * gm.x + be.x;
    float h1 = (fmaxf(a0.y + bb.y, 0.f) + r.y - mn.y) * rsqrtf(vr.y + EPS) * gm.y + be.y;
    float h2 = (fmaxf(a0.z + bb.z, 0.f) + r.z - mn.z) * rsqrtf(vr.z + EPS) * gm.z + be.z;
    float h3 = (fmaxf(a0.w + bb.w, 0.f) + r.w - mn.w) * rsqrtf(vr.w + EPS) * gm.w + be.w;

    int c = lane * 4;
    float l0 = h0 * wd[(c + 0) * 2] + h1 * wd[(c + 1) * 2] +
               h2 * wd[(c + 2) * 2] + h3 * wd[(c + 3) * 2];
    float l1 = h0 * wd[(c + 0) * 2 + 1] + h1 * wd[(c + 1) * 2 + 1] +
               h2 * wd[(c + 2) * 2 + 1] + h3 * wd[(c + 3) * 2 + 1];
#pragma unroll
    for (int off = 16; off > 0; off >>= 1) {
        l0 += __shfl_xor_sync(0xFFFFFFFFu, l0, off);
        l1 += __shfl_xor_sync(0xFFFFFFFFu, l1, off);
    }
    if (lane == 0) {
        l0 += __ldg(bd + 0);
        l1 += __ldg(bd + 1);
        float m  = fmaxf(l0, l1);
        float e0 = __expf(l0 - m), e1 = __expf(l1 - m);
        float inv = 1.f / (e0 + e1);
        out[(size_t)wid * 2 + 0] = e0 * inv;
        out[(size_t)wid * 2 + 1] = e1 * inv;
    }
}

// ---------------------------------------------------------------------------
extern "C" void kernel_launch(void* const* d_in, const int* in_sizes, int n_in,
                              void* d_out, int out_size)
{
    const float* in_feat = (const float*)d_in[0];
    const int*   src     = (const int*)d_in[1];
    const int*   dst     = (const int*)d_in[2];
    const float* W0   = (const float*)d_in[3];
    const float* b0   = (const float*)d_in[4];
    const float* Wr0  = (const float*)d_in[5];
    const float* br0  = (const float*)d_in[6];
    const float* g0   = (const float*)d_in[7];
    const float* be0  = (const float*)d_in[8];
    const float* m0   = (const float*)d_in[9];
    const float* v0   = (const float*)d_in[10];
    const float* W1   = (const float*)d_in[11];
    const float* b1   = (const float*)d_in[12];
    const float* Wr1  = (const float*)d_in[13];
    const float* br1  = (const float*)d_in[14];
    const float* g1   = (const float*)d_in[15];
    const float* be1  = (const float*)d_in[16];
    const float* m1   = (const float*)d_in[17];
    const float* v1   = (const float*)d_in[18];
    const float* Wd   = (const float*)d_in[19];
    const float* bd   = (const float*)d_in[20];

    const int N = in_sizes[0] / F_IN;   // 50000
    const int E = in_sizes[1];          // 800000

    constexpr int GEMM_SMEM = 6 * 128 * 40 * 2;   // 61440 bytes

    struct Ptrs {
        __nv_bfloat16 *msg, *res, *xbf, *hbf, *w0t, *wr0t, *w1t, *wr1t;
    };
    static Ptrs P = {};
    if (P.msg == nullptr) {
        cudaGetSymbolAddress((void**)&P.msg,  g_msg);
        cudaGetSymbolAddress((void**)&P.res,  g_res);
        cudaGetSymbolAddress((void**)&P.xbf,  g_Xbf);
        cudaGetSymbolAddress((void**)&P.hbf,  g_Hbf);
        cudaGetSymbolAddress((void**)&P.w0t,  g_W0t);
        cudaGetSymbolAddress((void**)&P.wr0t, g_Wr0t);
        cudaGetSymbolAddress((void**)&P.w1t,  g_W1t);
        cudaGetSymbolAddress((void**)&P.wr1t, g_Wr1t);
        cudaFuncSetAttribute(gemm_dual_kernel<F_IN>,
                             cudaFuncAttributeMaxDynamicSharedMemorySize, GEMM_SMEM);
        cudaFuncSetAttribute(gemm_dual_kernel<F_H>,
                             cudaFuncAttributeMaxDynamicSharedMemorySize, GEMM_SMEM);
    }

    const int NB = (N + 255) / 256;
    const int eb = (E + 255) / 256;
    const int x4 = N * (F_IN / 4);
    const int XB = (x4 + 255) / 256;
    const int gb = (N + 7) / 8;
    const int gemm_blocks = (N + 127) / 128;

    // fused conversions (X + all four weights)
    convAll_kernel<<<XB + 1152, 256>>>((const float4*)in_feat, (__nv_bfloat162*)P.xbf,
                                       x4, XB, W0, P.w0t, Wr0, P.wr0t, W1, P.w1t, Wr1, P.wr1t);

    // CSR build (shared by both layers)
    zerodeg_kernel<<<NB, 256>>>(N);
    hist_kernel<<<eb, 256>>>(dst, E);
    scan1_kernel<<<NB, 256>>>(N);
    scan2_kernel<<<1, 256>>>(NB);
    scan3_kernel<<<NB, 256>>>(N);
    fill_kernel<<<eb, 256>>>(src, dst, E);

    // Layer 0
    gemm_dual_kernel<F_IN><<<gemm_blocks, 256, GEMM_SMEM>>>(P.xbf, P.w0t, P.wr0t, br0,
                                                            P.msg, P.res, N);
    gather0_kernel<<<gb, 256>>>(P.msg, P.res, (const float4*)b0, (const float4*)g0,
                                (const float4*)be0, (const float4*)m0, (const float4*)v0,
                                (__nv_bfloat162*)P.hbf, N);

    // Layer 1
    gemm_dual_kernel<F_H><<<gemm_blocks, 256, GEMM_SMEM>>>(P.hbf, P.w1t, P.wr1t, br1,
                                                           P.msg, P.res, N);
    gather1_head_kernel<<<gb, 256>>>(P.msg, P.res, (const float4*)b1, (const float4*)g1,
                                     (const float4*)be1, (const float4*)m1, (const float4*)v1,
                                     Wd, bd, (float*)d_out, N);
}

// round 6
// speedup vs baseline: 5.8590x; 1.0652x over previous
#include <cuda_runtime.h>
#include <cuda_bf16.h>
#include <cstdint>

#define F_IN  1024
#define F_H   128
#define EPS   1e-5f
#define NODES_MAX 50048
#define EDGES_MAX 800000
#define SCAN_BLOCKS 256   // >= ceil(N/256)

// ------------------------- scratch (__device__ globals) ---------------------
__device__ __align__(256) __nv_bfloat16 g_msg[NODES_MAX * F_H];
__device__ __align__(256) __nv_bfloat16 g_res[NODES_MAX * F_H];
__device__ __align__(256) __nv_bfloat16 g_Hbf[NODES_MAX * F_H];
__device__ __align__(256) __nv_bfloat16 g_W0t [F_H * F_IN];
__device__ __align__(256) __nv_bfloat16 g_Wr0t[F_H * F_IN];
__device__ __align__(256) __nv_bfloat16 g_W1t [F_H * F_H];
__device__ __align__(256) __nv_bfloat16 g_Wr1t[F_H * F_H];
__device__ int g_deg [NODES_MAX];
__device__ int g_row [NODES_MAX];
__device__ int g_cur [NODES_MAX];
__device__ int g_esrc[EDGES_MAX];
__device__ unsigned int g_stat[SCAN_BLOCKS];   // lookback: (status<<30)|value

// ------------------------- weight conversion --------------------------------
// blocks [0,512): W0 -> W0t   [512,1024): Wr0 -> Wr0t
// [1024,1088): W1 -> W1t      [1088,1152): Wr1 -> Wr1t
__global__ void convW_kernel(const float* __restrict__ W0,  __nv_bfloat16* __restrict__ W0t,
                             const float* __restrict__ Wr0, __nv_bfloat16* __restrict__ Wr0t,
                             const float* __restrict__ W1,  __nv_bfloat16* __restrict__ W1t,
                             const float* __restrict__ Wr1, __nv_bfloat16* __restrict__ Wr1t)
{
    int b = blockIdx.x;
    const float* w; __nv_bfloat16* wt; int K;
    if (b < 512)        { w = W0;  wt = W0t;  K = F_IN; }
    else if (b < 1024)  { w = Wr0; wt = Wr0t; K = F_IN; b -= 512; }
    else if (b < 1088)  { w = W1;  wt = W1t;  K = F_H;  b -= 1024; }
    else                { w = Wr1; wt = Wr1t; K = F_H;  b -= 1088; }
    int idx = b * 256 + threadIdx.x;
    if (idx >= K * F_H) return;
    int k = idx >> 7, n = idx & 127;
    wt[(size_t)n * K + k] = __float2bfloat16(w[idx]);
}

// ------------------------- CSR build (side stream) --------------------------
__global__ void zero_kernel(int N)
{
    int i = blockIdx.x * blockDim.x + threadIdx.x;
    if (i < N) g_deg[i] = 0;
    if (i < SCAN_BLOCKS) g_stat[i] = 0;
}
__global__ void hist_kernel(const int* __restrict__ dst, int E)
{
    int e = blockIdx.x * blockDim.x + threadIdx.x;
    if (e < E) atomicAdd(&g_deg[dst[e]], 1);
}
// single-pass decoupled-lookback exclusive scan of g_deg -> g_row, g_cur
__global__ void scan_kernel(int N)
{
    __shared__ int s[256];
    __shared__ int s_prefix;
    const int t = threadIdx.x;
    const int bid = blockIdx.x;
    const int i = bid * 256 + t;
    int v = (i < N) ? g_deg[i] : 0;
    s[t] = v;
    __syncthreads();
#pragma unroll
    for (int off = 1; off < 256; off <<= 1) {
        int x = (t >= off) ? s[t - off] : 0;
        __syncthreads();
        s[t] += x;
        __syncthreads();
    }
    const int total = s[255];

    if (t == 0) {
        if (bid == 0) {
            __threadfence();
            atomicExch(&g_stat[0], (2u << 30) | (unsigned)total);
            s_prefix = 0;
        } else {
            __threadfence();
            atomicExch(&g_stat[bid], (1u << 30) | (unsigned)total);
            // lookback
            int ex = 0;
            int j = bid - 1;
            while (true) {
                unsigned w = atomicAdd(&g_stat[j], 0u);
                unsigned st = w >> 30;
                if (st == 0) continue;
                ex += (int)(w & 0x3FFFFFFFu);
                if (st == 2u) break;
                j--;
            }
            __threadfence();
            atomicExch(&g_stat[bid], (2u << 30) | (unsigned)(ex + total));
            s_prefix = ex;
        }
    }
    __syncthreads();
    if (i < N) {
        int r = s[t] - v + s_prefix;
        g_row[i] = r;
        g_cur[i] = r;
    }
}
__global__ void fill_kernel(const int* __restrict__ src, const int* __restrict__ dst, int E)
{
    int e = blockIdx.x * blockDim.x + threadIdx.x;
    if (e >= E) return;
    int d = dst[e];
    int pos = atomicAdd(&g_cur[d], 1);
    g_esrc[pos] = src[e];
}

// ------------------------- mma helper ---------------------------------------
__device__ __forceinline__ void mma_bf16(float* c, const uint32_t* a, const uint32_t* b)
{
    asm volatile(
        "mma.sync.aligned.m16n8k16.row.col.f32.bf16.bf16.f32 "
        "{%0,%1,%2,%3}, {%4,%5,%6,%7}, {%8,%9}, {%0,%1,%2,%3};"
        : "+f"(c[0]), "+f"(c[1]), "+f"(c[2]), "+f"(c[3])
        : "r"(a[0]), "r"(a[1]), "r"(a[2]), "r"(a[3]), "r"(b[0]), "r"(b[1]));
}

// ------------------------- GEMM0: fp32 X, fused bf16 convert ----------------
// One CTA: 128 M-rows, both outputs. X fp32 staged in registers (1-ahead),
// converted to bf16 into single-buffered smem A tile. W/R bf16 cp.async 2-stage.
__global__ void __launch_bounds__(256) gemm0_kernel(
    const float* __restrict__ Xf, const __nv_bfloat16* __restrict__ Wt,
    const __nv_bfloat16* __restrict__ Wrt, const float* __restrict__ br,
    __nv_bfloat16* __restrict__ out_msg, __nv_bfloat16* __restrict__ out_res, int M)
{
    constexpr int KD = F_IN, BM = 128, BK = 32;
    constexpr int NIT = KD / BK;      // 32
    constexpr int SA = 40;            // bf16 row stride (32 + 8 pad)
    constexpr int TILE = BM * SA;     // 5120 bf16
    extern __shared__ __align__(16) __nv_bfloat16 smem[];
    __nv_bfloat16* sAb = smem;                 // single buffer
    __nv_bfloat16* sW  = smem + TILE;          // 2 stages
    __nv_bfloat16* sR  = smem + 3 * TILE;      // 2 stages

    const int t = threadIdx.x;
    const int bm = blockIdx.x * BM;
    const int lane = t & 31;
    const int w    = t >> 5;
    const int wm   = (w & 1) * 64;
    const int wn   = (w >> 1) * 32;
    const int g    = lane >> 2;
    const int t4   = lane & 3;

    const uint32_t sAb_u = (uint32_t)__cvta_generic_to_shared(sAb);
    const uint32_t sW_u  = (uint32_t)__cvta_generic_to_shared(sW);
    const uint32_t sR_u  = (uint32_t)__cvta_generic_to_shared(sR);

    // A staging: row = t&127, half = t>>7 (16 fp32 each)
    const int arow = t & 127;
    const int ah   = t >> 7;
    const bool aok = (bm + arow) < M;
    const float* aptr_base = Xf + (size_t)(bm + arow) * KD + ah * 16;

    float4 areg[4];
    {
        const float4* p = (const float4*)aptr_base;   // k0 = 0
        if (aok) { areg[0] = p[0]; areg[1] = p[1]; areg[2] = p[2]; areg[3] = p[3]; }
        else     { areg[0] = areg[1] = areg[2] = areg[3] = make_float4(0,0,0,0); }
    }

    auto loadWR = [&](int it, int stg) {
        const int k0 = it * BK;
#pragma unroll
        for (int i = 0; i < 2; i++) {
            int lin = t + i * 256;
            int m = lin >> 2, q = lin & 3;
            uint32_t doff = (uint32_t)((stg * TILE + m * SA + q * 8) * 2);
            const __nv_bfloat16* wsrc = Wt + (size_t)m * KD + k0 + q * 8;
            asm volatile("cp.async.cg.shared.global [%0], [%1], 16, 16;\n"
                         :: "r"(sW_u + doff), "l"(wsrc));
            const __nv_bfloat16* rsrc = Wrt + (size_t)m * KD + k0 + q * 8;
            asm volatile("cp.async.cg.shared.global [%0], [%1], 16, 16;\n"
                         :: "r"(sR_u + doff), "l"(rsrc));
        }
        asm volatile("cp.async.commit_group;\n");
    };

    loadWR(0, 0);

    float acc[2][4][4][4];
#pragma unroll
    for (int o = 0; o < 2; o++)
#pragma unroll
        for (int i = 0; i < 4; i++)
#pragma unroll
            for (int j = 0; j < 4; j++)
#pragma unroll
                for (int k = 0; k < 4; k++) acc[o][i][j][k] = 0.f;

    const int mrow = lane & 15;
    const int ksel = (lane >> 4) * 8;
    const int b_nrow = ((lane >> 4) & 1) * 8 + (lane & 7);
    const int b_koff = ((lane >> 3) & 1) * 8;
    const uint32_t asts = sAb_u + (uint32_t)((arow * SA + ah * 16) * 2);

    for (int it = 0; it < NIT; ++it) {
        const int stg = it & 1;
        __syncthreads();                       // all warps done with sAb + stg^1 W/R
        if (it + 1 < NIT) loadWR(it + 1, stg ^ 1);
        // convert areg (stage it) -> sAb
        {
            uint4 lo, hi;
            __nv_bfloat162 p;
            p = __float22bfloat162_rn(make_float2(areg[0].x, areg[0].y)); lo.x = *(uint32_t*)&p;
            p = __float22bfloat162_rn(make_float2(areg[0].z, areg[0].w)); lo.y = *(uint32_t*)&p;
            p = __float22bfloat162_rn(make_float2(areg[1].x, areg[1].y)); lo.z = *(uint32_t*)&p;
            p = __float22bfloat162_rn(make_float2(areg[1].z, areg[1].w)); lo.w = *(uint32_t*)&p;
            p = __float22bfloat162_rn(make_float2(areg[2].x, areg[2].y)); hi.x = *(uint32_t*)&p;
            p = __float22bfloat162_rn(make_float2(areg[2].z, areg[2].w)); hi.y = *(uint32_t*)&p;
            p = __float22bfloat162_rn(make_float2(areg[3].x, areg[3].y)); hi.z = *(uint32_t*)&p;
            p = __float22bfloat162_rn(make_float2(areg[3].z, areg[3].w)); hi.w = *(uint32_t*)&p;
            asm volatile("st.shared.v4.b32 [%0], {%1,%2,%3,%4};"
                         :: "r"(asts), "r"(lo.x), "r"(lo.y), "r"(lo.z), "r"(lo.w));
            asm volatile("st.shared.v4.b32 [%0], {%1,%2,%3,%4};"
                         :: "r"(asts + 16), "r"(hi.x), "r"(hi.y), "r"(hi.z), "r"(hi.w));
        }
        // prefetch next A stage into registers
        if (it + 1 < NIT) {
            const float4* p = (const float4*)(aptr_base + (it + 1) * BK);
            if (aok) { areg[0] = p[0]; areg[1] = p[1]; areg[2] = p[2]; areg[3] = p[3]; }
        }
        if (it + 1 < NIT) asm volatile("cp.async.wait_group 1;\n");
        else              asm volatile("cp.async.wait_group 0;\n");
        __syncthreads();

        const uint32_t W_u = sW_u + (uint32_t)(stg * TILE * 2);
        const uint32_t R_u = sR_u + (uint32_t)(stg * TILE * 2);

#pragma unroll
        for (int ks = 0; ks < 2; ks++) {
            const int kb = ks * 16;
            uint32_t a[4][4];
#pragma unroll
            for (int ma = 0; ma < 4; ma++) {
                uint32_t addr = sAb_u + (uint32_t)(((wm + ma * 16 + mrow) * SA + kb + ksel) * 2);
                asm volatile("ldmatrix.sync.aligned.m8n8.x4.shared.b16 {%0,%1,%2,%3}, [%4];"
                             : "=r"(a[ma][0]), "=r"(a[ma][1]), "=r"(a[ma][2]), "=r"(a[ma][3])
                             : "r"(addr));
            }
#pragma unroll
            for (int o = 0; o < 2; o++) {
                const uint32_t B_u = o ? R_u : W_u;
#pragma unroll
                for (int pr = 0; pr < 2; pr++) {
                    uint32_t b0, b1, b2, b3;
                    uint32_t addr = B_u + (uint32_t)(((wn + pr * 16 + b_nrow) * SA + kb + b_koff) * 2);
                    asm volatile("ldmatrix.sync.aligned.m8n8.x4.shared.b16 {%0,%1,%2,%3}, [%4];"
                                 : "=r"(b0), "=r"(b1), "=r"(b2), "=r"(b3)
                                 : "r"(addr));
                    uint32_t bl[2] = {b0, b1};
                    uint32_t bh[2] = {b2, b3};
#pragma unroll
                    for (int ma = 0; ma < 4; ma++) {
                        mma_bf16(acc[o][ma][pr * 2],     a[ma], bl);
                        mma_bf16(acc[o][ma][pr * 2 + 1], a[ma], bh);
                    }
                }
            }
        }
    }

    // Epilogue: bf16 outputs; res gets +br then relu
#pragma unroll
    for (int o = 0; o < 2; o++) {
        __nv_bfloat16* __restrict__ out = o ? out_res : out_msg;
#pragma unroll
        for (int nb = 0; nb < 4; nb++) {
            const int col = wn + nb * 8 + 2 * t4;
            float2 brv = make_float2(0.f, 0.f);
            if (o) { brv.x = br[col]; brv.y = br[col + 1]; }
#pragma unroll
            for (int ma = 0; ma < 4; ma++) {
                int row0 = bm + wm + ma * 16 + g;
                float* c = acc[o][ma][nb];
                float2 v0 = make_float2(c[0], c[1]);
                float2 v1 = make_float2(c[2], c[3]);
                if (o) {
                    v0.x = fmaxf(v0.x + brv.x, 0.f); v0.y = fmaxf(v0.y + brv.y, 0.f);
                    v1.x = fmaxf(v1.x + brv.x, 0.f); v1.y = fmaxf(v1.y + brv.y, 0.f);
                }
                __nv_bfloat162 p0, p1;
                p0.x = __float2bfloat16(v0.x); p0.y = __float2bfloat16(v0.y);
                p1.x = __float2bfloat16(v1.x); p1.y = __float2bfloat16(v1.y);
                if (row0 < M)
                    *(__nv_bfloat162*)(out + (size_t)row0 * F_H + col) = p0;
                if (row0 + 8 < M)
                    *(__nv_bfloat162*)(out + (size_t)(row0 + 8) * F_H + col) = p1;
            }
        }
    }
}

// ------------------------- GEMM1: bf16 input (R5 kernel) --------------------
template <int KD>
__global__ void __launch_bounds__(256) gemm_dual_kernel(
    const __nv_bfloat16* __restrict__ Xb, const __nv_bfloat16* __restrict__ Wt,
    const __nv_bfloat16* __restrict__ Wrt, const float* __restrict__ br,
    __nv_bfloat16* __restrict__ out_msg, __nv_bfloat16* __restrict__ out_res, int M)
{
    constexpr int BM = 128, BK = 32;
    constexpr int NIT = KD / BK;
    constexpr int SA = 40;
    constexpr int TILE = BM * SA;
    extern __shared__ __align__(16) __nv_bfloat16 smem[];
    __nv_bfloat16* sA = smem;
    __nv_bfloat16* sW = smem + 2 * TILE;
    __nv_bfloat16* sR = smem + 4 * TILE;

    const int t = threadIdx.x;
    const int bm = blockIdx.x * BM;
    const int lane = t & 31;
    const int w    = t >> 5;
    const int wm   = (w & 1) * 64;
    const int wn   = (w >> 1) * 32;
    const int g    = lane >> 2;
    const int t4   = lane & 3;

    const uint32_t sA_u = (uint32_t)__cvta_generic_to_shared(sA);
    const uint32_t sW_u = (uint32_t)__cvta_generic_to_shared(sW);
    const uint32_t sR_u = (uint32_t)__cvta_generic_to_shared(sR);

    float acc[2][4][4][4];
#pragma unroll
    for (int o = 0; o < 2; o++)
#pragma unroll
        for (int i = 0; i < 4; i++)
#pragma unroll
            for (int j = 0; j < 4; j++)
#pragma unroll
                for (int k = 0; k < 4; k++) acc[o][i][j][k] = 0.f;

    auto loadStage = [&](int it, int stg) {
        const int k0 = it * BK;
#pragma unroll
        for (int i = 0; i < 2; i++) {
            int lin = t + i * 256;
            int m = lin >> 2, q = lin & 3;
            uint32_t doff = (uint32_t)((stg * TILE + m * SA + q * 8) * 2);
            const __nv_bfloat16* asrc = Xb + (size_t)(bm + m) * KD + k0 + q * 8;
            int sz = (bm + m < M) ? 16 : 0;
            asm volatile("cp.async.cg.shared.global [%0], [%1], 16, %2;\n"
                         :: "r"(sA_u + doff), "l"(asrc), "r"(sz));
            const __nv_bfloat16* wsrc = Wt + (size_t)m * KD + k0 + q * 8;
            asm volatile("cp.async.cg.shared.global [%0], [%1], 16, 16;\n"
                         :: "r"(sW_u + doff), "l"(wsrc));
            const __nv_bfloat16* rsrc = Wrt + (size_t)m * KD + k0 + q * 8;
            asm volatile("cp.async.cg.shared.global [%0], [%1], 16, 16;\n"
                         :: "r"(sR_u + doff), "l"(rsrc));
        }
        asm volatile("cp.async.commit_group;\n");
    };

    loadStage(0, 0);

    const int mrow = lane & 15;
    const int ksel = (lane >> 4) * 8;
    const int b_nrow = ((lane >> 4) & 1) * 8 + (lane & 7);
    const int b_koff = ((lane >> 3) & 1) * 8;

    for (int it = 0; it < NIT; ++it) {
        const int stg = it & 1;
        if (it + 1 < NIT) {
            loadStage(it + 1, stg ^ 1);
            asm volatile("cp.async.wait_group 1;\n");
        } else {
            asm volatile("cp.async.wait_group 0;\n");
        }
        __syncthreads();

        const uint32_t A_u = sA_u + (uint32_t)(stg * TILE * 2);
        const uint32_t W_u = sW_u + (uint32_t)(stg * TILE * 2);
        const uint32_t R_u = sR_u + (uint32_t)(stg * TILE * 2);

#pragma unroll
        for (int ks = 0; ks < 2; ks++) {
            const int kb = ks * 16;
            uint32_t a[4][4];
#pragma unroll
            for (int ma = 0; ma < 4; ma++) {
                uint32_t addr = A_u + (uint32_t)(((wm + ma * 16 + mrow) * SA + kb + ksel) * 2);
                asm volatile("ldmatrix.sync.aligned.m8n8.x4.shared.b16 {%0,%1,%2,%3}, [%4];"
                             : "=r"(a[ma][0]), "=r"(a[ma][1]), "=r"(a[ma][2]), "=r"(a[ma][3])
                             : "r"(addr));
            }
#pragma unroll
            for (int o = 0; o < 2; o++) {
                const uint32_t B_u = o ? R_u : W_u;
#pragma unroll
                for (int pr = 0; pr < 2; pr++) {
                    uint32_t b0, b1, b2, b3;
                    uint32_t addr = B_u + (uint32_t)(((wn + pr * 16 + b_nrow) * SA + kb + b_koff) * 2);
                    asm volatile("ldmatrix.sync.aligned.m8n8.x4.shared.b16 {%0,%1,%2,%3}, [%4];"
                                 : "=r"(b0), "=r"(b1), "=r"(b2), "=r"(b3)
                                 : "r"(addr));
                    uint32_t bl[2] = {b0, b1};
                    uint32_t bh[2] = {b2, b3};
#pragma unroll
                    for (int ma = 0; ma < 4; ma++) {
                        mma_bf16(acc[o][ma][pr * 2],     a[ma], bl);
                        mma_bf16(acc[o][ma][pr * 2 + 1], a[ma], bh);
                    }
                }
            }
        }
        __syncthreads();
    }

#pragma unroll
    for (int o = 0; o < 2; o++) {
        __nv_bfloat16* __restrict__ out = o ? out_res : out_msg;
#pragma unroll
        for (int nb = 0; nb < 4; nb++) {
            const int col = wn + nb * 8 + 2 * t4;
            float2 brv = make_float2(0.f, 0.f);
            if (o) { brv.x = br[col]; brv.y = br[col + 1]; }
#pragma unroll
            for (int ma = 0; ma < 4; ma++) {
                int row0 = bm + wm + ma * 16 + g;
                float* c = acc[o][ma][nb];
                float2 v0 = make_float2(c[0], c[1]);
                float2 v1 = make_float2(c[2], c[3]);
                if (o) {
                    v0.x = fmaxf(v0.x + brv.x, 0.f); v0.y = fmaxf(v0.y + brv.y, 0.f);
                    v1.x = fmaxf(v1.x + brv.x, 0.f); v1.y = fmaxf(v1.y + brv.y, 0.f);
                }
                __nv_bfloat162 p0, p1;
                p0.x = __float2bfloat16(v0.x); p0.y = __float2bfloat16(v0.y);
                p1.x = __float2bfloat16(v1.x); p1.y = __float2bfloat16(v1.y);
                if (row0 < M)
                    *(__nv_bfloat162*)(out + (size_t)row0 * F_H + col) = p0;
                if (row0 + 8 < M)
                    *(__nv_bfloat162*)(out + (size_t)(row0 + 8) * F_H + col) = p1;
            }
        }
    }
}

// ------------------------- gather + fused epilogues -------------------------
__device__ __forceinline__ void acc_row(const __nv_bfloat16* __restrict__ base,
                                        int node, int lane, float4& a)
{
    uint2 q = __ldg((const uint2*)(base + (size_t)node * F_H) + lane);
    __nv_bfloat162 x0 = *(__nv_bfloat162*)&q.x;
    __nv_bfloat162 x1 = *(__nv_bfloat162*)&q.y;
    float2 f0 = __bfloat1622float2(x0);
    float2 f1 = __bfloat1622float2(x1);
    a.x += f0.x; a.y += f0.y; a.z += f1.x; a.w += f1.y;
}

__global__ void gather0_kernel(const __nv_bfloat16* __restrict__ msg,
                               const __nv_bfloat16* __restrict__ res,
                               const float4* __restrict__ b4, const float4* __restrict__ g4,
                               const float4* __restrict__ be4, const float4* __restrict__ mn4,
                               const float4* __restrict__ vr4,
                               __nv_bfloat162* __restrict__ hout, int N)
{
    int wid  = (blockIdx.x * blockDim.x + threadIdx.x) >> 5;
    int lane = threadIdx.x & 31;
    if (wid >= N) return;
    int s = g_row[wid], e = g_cur[wid];

    float4 a0 = make_float4(0.f, 0.f, 0.f, 0.f);
    float4 a1 = make_float4(0.f, 0.f, 0.f, 0.f);
    int i = s;
    for (; i + 2 <= e; i += 2) {
        int u = __ldg(&g_esrc[i]), v = __ldg(&g_esrc[i + 1]);
        acc_row(msg, u, lane, a0);
        acc_row(msg, v, lane, a1);
    }
    if (i < e) acc_row(msg, __ldg(&g_esrc[i]), lane, a0);
    a0.x += a1.x; a0.y += a1.y; a0.z += a1.z; a0.w += a1.w;

    float4 r = make_float4(0.f, 0.f, 0.f, 0.f);
    acc_row(res, wid, lane, r);
    float4 bb = __ldg(b4 + lane);
    float4 gm = __ldg(g4 + lane);
    float4 be = __ldg(be4 + lane);
    float4 mn = __ldg(mn4 + lane);
    float4 vr = __ldg(vr4 + lane);
    float o0 = (fmaxf(a0.x + bb.x, 0.f) + r.x - mn.x) * rsqrtf(vr.x + EPS) * gm.x + be.x;
    float o1 = (fmaxf(a0.y + bb.y, 0.f) + r.y - mn.y) * rsqrtf(vr.y + EPS) * gm.y + be.y;
    float o2 = (fmaxf(a0.z + bb.z, 0.f) + r.z - mn.z) * rsqrtf(vr.z + EPS) * gm.z + be.z;
    float o3 = (fmaxf(a0.w + bb.w, 0.f) + r.w - mn.w) * rsqrtf(vr.w + EPS) * gm.w + be.w;

    __nv_bfloat162 p0, p1;
    p0.x = __float2bfloat16(o0); p0.y = __float2bfloat16(o1);
    p1.x = __float2bfloat16(o2); p1.y = __float2bfloat16(o3);
    hout[(size_t)wid * (F_H / 2) + lane * 2]     = p0;
    hout[(size_t)wid * (F_H / 2) + lane * 2 + 1] = p1;
}

__global__ void gather1_head_kernel(const __nv_bfloat16* __restrict__ msg,
                                    const __nv_bfloat16* __restrict__ res,
                                    const float4* __restrict__ b4, const float4* __restrict__ g4,
                                    const float4* __restrict__ be4, const float4* __restrict__ mn4,
                                    const float4* __restrict__ vr4,
                                    const float* __restrict__ Wd, const float* __restrict__ bd,
                                    float* __restrict__ out, int N)
{
    __shared__ float wd[F_H * 2];
    wd[threadIdx.x] = Wd[threadIdx.x];
    __syncthreads();

    int wid  = (blockIdx.x * blockDim.x + threadIdx.x) >> 5;
    int lane = threadIdx.x & 31;
    if (wid >= N) return;
    int s = g_row[wid], e = g_cur[wid];

    float4 a0 = make_float4(0.f, 0.f, 0.f, 0.f);
    float4 a1 = make_float4(0.f, 0.f, 0.f, 0.f);
    int i = s;
    for (; i + 2 <= e; i += 2) {
        int u = __ldg(&g_esrc[i]), v = __ldg(&g_esrc[i + 1]);
        acc_row(msg, u, lane, a0);
        acc_row(msg, v, lane, a1);
    }
    if (i < e) acc_row(msg, __ldg(&g_esrc[i]), lane, a0);
    a0.x += a1.x; a0.y += a1.y; a0.z += a1.z; a0.w += a1.w;

    float4 r = make_float4(0.f, 0.f, 0.f, 0.f);
    acc_row(res, wid, lane, r);
    float4 bb = __ldg(b4 + lane);
    float4 gm = __ldg(g4 + lane);
    float4 be = __ldg(be4 + lane);
    float4 mn = __ldg(mn4 + lane);
    float4 vr = __ldg(vr4 + lane);
    float h0 = (fmaxf(a0.x + bb.x, 0.f) + r.x - mn.x) * rsqrtf(vr.x + EPS) * gm.x + be.x;
    float h1 = (fmaxf(a0.y + bb.y, 0.f) + r.y - mn.y) * rsqrtf(vr.y + EPS) * gm.y + be.y;
    float h2 = (fmaxf(a0.z + bb.z, 0.f) + r.z - mn.z) * rsqrtf(vr.z + EPS) * gm.z + be.z;
    float h3 = (fmaxf(a0.w + bb.w, 0.f) + r.w - mn.w) * rsqrtf(vr.w + EPS) * gm.w + be.w;

    int c = lane * 4;
    float l0 = h0 * wd[(c + 0) * 2] + h1 * wd[(c + 1) * 2] +
               h2 * wd[(c + 2) * 2] + h3 * wd[(c + 3) * 2];
    float l1 = h0 * wd[(c + 0) * 2 + 1] + h1 * wd[(c + 1) * 2 + 1] +
               h2 * wd[(c + 2) * 2 + 1] + h3 * wd[(c + 3) * 2 + 1];
#pragma unroll
    for (int off = 16; off > 0; off >>= 1) {
        l0 += __shfl_xor_sync(0xFFFFFFFFu, l0, off);
        l1 += __shfl_xor_sync(0xFFFFFFFFu, l1, off);
    }
    if (lane == 0) {
        l0 += __ldg(bd + 0);
        l1 += __ldg(bd + 1);
        float m  = fmaxf(l0, l1);
        float e0 = __expf(l0 - m), e1 = __expf(l1 - m);
        float inv = 1.f / (e0 + e1);
        out[(size_t)wid * 2 + 0] = e0 * inv;
        out[(size_t)wid * 2 + 1] = e1 * inv;
    }
}

// ---------------------------------------------------------------------------
extern "C" void kernel_launch(void* const* d_in, const int* in_sizes, int n_in,
                              void* d_out, int out_size)
{
    const float* in_feat = (const float*)d_in[0];
    const int*   src     = (const int*)d_in[1];
    const int*   dst     = (const int*)d_in[2];
    const float* W0   = (const float*)d_in[3];
    const float* b0   = (const float*)d_in[4];
    const float* Wr0  = (const float*)d_in[5];
    const float* br0  = (const float*)d_in[6];
    const float* g0   = (const float*)d_in[7];
    const float* be0  = (const float*)d_in[8];
    const float* m0   = (const float*)d_in[9];
    const float* v0   = (const float*)d_in[10];
    const float* W1   = (const float*)d_in[11];
    const float* b1   = (const float*)d_in[12];
    const float* Wr1  = (const float*)d_in[13];
    const float* br1  = (const float*)d_in[14];
    const float* g1   = (const float*)d_in[15];
    const float* be1  = (const float*)d_in[16];
    const float* m1   = (const float*)d_in[17];
    const float* v1   = (const float*)d_in[18];
    const float* Wd   = (const float*)d_in[19];
    const float* bd   = (const float*)d_in[20];

    const int N = in_sizes[0] / F_IN;   // 50000
    const int E = in_sizes[1];          // 800000

    constexpr int GEMM0_SMEM = 5 * 128 * 40 * 2;   // 51200 bytes (A x1 + W x2 + R x2)
    constexpr int GEMM1_SMEM = 6 * 128 * 40 * 2;   // 61440 bytes

    struct Ctx {
        __nv_bfloat16 *msg, *res, *hbf, *w0t, *wr0t, *w1t, *wr1t;
        cudaStream_t s2;
        cudaEvent_t evFork, evJoin;
        bool init;
    };
    static Ctx C = {};
    if (!C.init) {
        cudaGetSymbolAddress((void**)&C.msg,  g_msg);
        cudaGetSymbolAddress((void**)&C.res,  g_res);
        cudaGetSymbolAddress((void**)&C.hbf,  g_Hbf);
        cudaGetSymbolAddress((void**)&C.w0t,  g_W0t);
        cudaGetSymbolAddress((void**)&C.wr0t, g_Wr0t);
        cudaGetSymbolAddress((void**)&C.w1t,  g_W1t);
        cudaGetSymbolAddress((void**)&C.wr1t, g_Wr1t);
        cudaFuncSetAttribute(gemm0_kernel,
                             cudaFuncAttributeMaxDynamicSharedMemorySize, GEMM0_SMEM);
        cudaFuncSetAttribute(gemm_dual_kernel<F_H>,
                             cudaFuncAttributeMaxDynamicSharedMemorySize, GEMM1_SMEM);
        cudaStreamCreateWithFlags(&C.s2, cudaStreamNonBlocking);
        cudaEventCreateWithFlags(&C.evFork, cudaEventDisableTiming);
        cudaEventCreateWithFlags(&C.evJoin, cudaEventDisableTiming);
        C.init = true;
    }

    const int NB = (N + 255) / 256;
    const int eb = (E + 255) / 256;
    const int gb = (N + 7) / 8;
    const int gemm_blocks = (N + 127) / 128;

    // fork: CSR build on side stream
    cudaEventRecord(C.evFork, 0);
    cudaStreamWaitEvent(C.s2, C.evFork, 0);
    zero_kernel<<<NB, 256, 0, C.s2>>>(N);
    hist_kernel<<<eb, 256, 0, C.s2>>>(dst, E);
    scan_kernel<<<NB, 256, 0, C.s2>>>(N);
    fill_kernel<<<eb, 256, 0, C.s2>>>(src, dst, E);
    cudaEventRecord(C.evJoin, C.s2);

    // main stream: weights, GEMM0
    convW_kernel<<<1152, 256>>>(W0, C.w0t, Wr0, C.wr0t, W1, C.w1t, Wr1, C.wr1t);
    gemm0_kernel<<<gemm_blocks, 256, GEMM0_SMEM>>>(in_feat, C.w0t, C.wr0t, br0,
                                                   C.msg, C.res, N);

    // join: gathers need CSR
    cudaStreamWaitEvent(0, C.evJoin, 0);
    gather0_kernel<<<gb, 256>>>(C.msg, C.res, (const float4*)b0, (const float4*)g0,
                                (const float4*)be0, (const float4*)m0, (const float4*)v0,
                                (__nv_bfloat162*)C.hbf, N);

    gemm_dual_kernel<F_H><<<gemm_blocks, 256, GEMM1_SMEM>>>(C.hbf, C.w1t, C.wr1t, br1,
                                                            C.msg, C.res, N);
    gather1_head_kernel<<<gb, 256>>>(C.msg, C.res, (const float4*)b1, (const float4*)g1,
                                     (const float4*)be1, (const float4*)m1, (const float4*)v1,
                                     Wd, bd, (float*)d_out, N);
}